// round 8
// baseline (speedup 1.0000x reference)
#include <cuda_runtime.h>
#include <cuda_bf16.h>
#include <math.h>
#include <stdint.h>

#define B_   4
#define N_   1024
#define D_   1024
#define H_   16
#define HD_  64
#define FF_  4096
#define M_   (B_ * N_)   // 4096 rows

// ---------------- scratch (static device globals; no allocs allowed) ----------------
__device__ float g_t [M_ * D_];   // src2 / ffn2 output temp (fp32)
__device__ float g_x [M_ * D_];   // post-LN1 activations (fp32)

// bf16 hi/lo split buffers
__device__ __nv_bfloat16 s_src_h[M_ * D_],  s_src_l[M_ * D_];
__device__ __nv_bfloat16 s_wq_h [D_ * D_],  s_wq_l [D_ * D_];
__device__ __nv_bfloat16 s_wk_h [D_ * D_],  s_wk_l [D_ * D_];
__device__ __nv_bfloat16 s_wv_h [D_ * D_],  s_wv_l [D_ * D_];
__device__ __nv_bfloat16 s_wo_h [D_ * D_],  s_wo_l [D_ * D_];
__device__ __nv_bfloat16 s_w1_h [FF_ * D_], s_w1_l [FF_ * D_];
__device__ __nv_bfloat16 s_w2_h [D_ * FF_], s_w2_l [D_ * FF_];
__device__ __nv_bfloat16 s_x_h  [M_ * D_],  s_x_l  [M_ * D_];
__device__ __nv_bfloat16 s_ao_h [M_ * D_],  s_ao_l [M_ * D_];
__device__ __nv_bfloat16 s_ff_h [M_ * FF_], s_ff_l [M_ * FF_];
__device__ __nv_bfloat16 s_q_h  [M_ * D_],  s_q_l  [M_ * D_];
__device__ __nv_bfloat16 s_k_h  [M_ * D_],  s_k_l  [M_ * D_];
__device__ __nv_bfloat16 s_v_h  [M_ * D_],  s_v_l  [M_ * D_];

// ---------------- PTX helpers (Ampere-era only: valid at compute_103 base) ----------
__device__ __forceinline__ uint32_t s2u(const void* p) {
    uint32_t a;
    asm("{ .reg .u64 t; cvta.to.shared.u64 t, %1; cvt.u32.u64 %0, t; }" : "=r"(a) : "l"(p));
    return a;
}
__device__ __forceinline__ void cp_async16(uint32_t saddr, const void* g) {
    asm volatile("cp.async.cg.shared.global [%0], [%1], 16;" :: "r"(saddr), "l"(g) : "memory");
}
#define CP_COMMIT()  asm volatile("cp.async.commit_group;" ::: "memory")
#define CP_WAIT(n)   asm volatile("cp.async.wait_group %0;" :: "n"(n) : "memory")

__device__ __forceinline__ void ldsm4(uint32_t* r, uint32_t addr) {
    asm volatile("ldmatrix.sync.aligned.m8n8.x4.shared.b16 {%0,%1,%2,%3}, [%4];"
                 : "=r"(r[0]), "=r"(r[1]), "=r"(r[2]), "=r"(r[3]) : "r"(addr));
}
__device__ __forceinline__ void ldsm4t(uint32_t* r, uint32_t addr) {
    asm volatile("ldmatrix.sync.aligned.m8n8.x4.trans.shared.b16 {%0,%1,%2,%3}, [%4];"
                 : "=r"(r[0]), "=r"(r[1]), "=r"(r[2]), "=r"(r[3]) : "r"(addr));
}
__device__ __forceinline__ void mma16816(float* c, const uint32_t* a, const uint32_t* b) {
    asm volatile(
        "mma.sync.aligned.m16n8k16.row.col.f32.bf16.bf16.f32 "
        "{%0,%1,%2,%3}, {%4,%5,%6,%7}, {%8,%9}, {%0,%1,%2,%3};"
        : "+f"(c[0]), "+f"(c[1]), "+f"(c[2]), "+f"(c[3])
        : "r"(a[0]), "r"(a[1]), "r"(a[2]), "r"(a[3]), "r"(b[0]), "r"(b[1]));
}

#define SWZ(o) ((o) ^ (((o) >> 3) & 0x70))

__device__ __forceinline__ void pack_hl(float a, float b, uint32_t& hi, uint32_t& lo) {
    __nv_bfloat16 ha = __float2bfloat16(a), hb = __float2bfloat16(b);
    __nv_bfloat162 hp = __halves2bfloat162(ha, hb);
    hi = *(uint32_t*)&hp;
    __nv_bfloat162 lp = __halves2bfloat162(
        __float2bfloat16(a - __bfloat162float(ha)),
        __float2bfloat16(b - __bfloat162float(hb)));
    lo = *(uint32_t*)&lp;
}

// ---------------- split fp32 -> bf16 (hi, lo) ----------------
__global__ __launch_bounds__(256)
void split_kernel(const float4* __restrict__ x, uint2* __restrict__ hi,
                  uint2* __restrict__ lo, int n4) {
    int i = blockIdx.x * 256 + threadIdx.x;
    if (i >= n4) return;
    float4 v = x[i];
    uint32_t h0, l0, h1, l1;
    pack_hl(v.x, v.y, h0, l0);
    pack_hl(v.z, v.w, h1, l1);
    hi[i] = make_uint2(h0, h1);
    lo[i] = make_uint2(l0, l1);
}

// ---------------- HMMA GEMM body: 128x128 tile, 128 threads, warptile 64x64 --------
// BK=64, 3-stage cp.async. stage: Ah[0,16K) Al[16K,32K) Wh[32K,48K) Wl[48K,64K)
#define STAGE_BYTES 65536
#define GEMM_STAGES 3
#define GEMM_SMEM_BYTES (GEMM_STAGES * STAGE_BYTES)
#define GEMM_THREADS 128

template <int ACT, int OUTBF16>
__device__ __forceinline__
void gemm_body(const __nv_bfloat16* __restrict__ Ah, const __nv_bfloat16* __restrict__ Al,
               const __nv_bfloat16* __restrict__ Wh, const __nv_bfloat16* __restrict__ Wl,
               const float* __restrict__ bias,
               float* __restrict__ Cf,
               __nv_bfloat16* __restrict__ Ch, __nv_bfloat16* __restrict__ Cl,
               int Nn, int K, int mBase, int nBase, char* dsm) {
    const uint32_t sb = s2u(dsm);

    const int tid  = threadIdx.x;
    const int wid  = tid >> 5;
    const int lane = tid & 31;
    const int wm   = wid & 1;        // 2 warps in m (64 rows each)
    const int wn   = wid >> 1;       // 2 warps in n (64 cols each)
    const int NC = K / 64;

    const int r0 = tid >> 3;         // 0..15
    const int c0 = tid & 7;

    const __nv_bfloat16* pAh = Ah + (size_t)(mBase + r0) * K + c0 * 8;
    const __nv_bfloat16* pAl = Al + (size_t)(mBase + r0) * K + c0 * 8;
    const __nv_bfloat16* pWh = Wh + (size_t)(nBase + r0) * K + c0 * 8;
    const __nv_bfloat16* pWl = Wl + (size_t)(nBase + r0) * K + c0 * 8;

    auto load_stage = [&](int buf, int kcol) {
        const uint32_t stage = sb + buf * STAGE_BYTES;
#pragma unroll
        for (int j = 0; j < 8; j++) {
            const int r = r0 + 16 * j;
            const uint32_t off = SWZ((uint32_t)(r * 128 + c0 * 16));
            cp_async16(stage + off,         pAh + (size_t)(16 * j) * K + kcol);
            cp_async16(stage + 16384 + off, pAl + (size_t)(16 * j) * K + kcol);
            cp_async16(stage + 32768 + off, pWh + (size_t)(16 * j) * K + kcol);
            cp_async16(stage + 49152 + off, pWl + (size_t)(16 * j) * K + kcol);
        }
    };

    float acc[4][8][4];
#pragma unroll
    for (int i = 0; i < 4; i++)
#pragma unroll
        for (int j = 0; j < 8; j++)
#pragma unroll
            for (int t = 0; t < 4; t++) acc[i][j][t] = 0.f;

    const int aRow = wm * 64 + (lane & 15);
    const int aColSel = (lane >> 4) * 8;
    const int bRow = wn * 64 + ((lane >> 4) << 3) + (lane & 7);
    const int bColSel = ((lane >> 3) & 1) * 8;

    load_stage(0, 0);
    CP_COMMIT();
    load_stage(1, 64);
    CP_COMMIT();

    for (int c = 0; c < NC; c++) {
        if (c + 2 < NC) { CP_WAIT(1); }
        else            { CP_WAIT(0); }
        __syncthreads();

        const uint32_t stage = sb + (c % GEMM_STAGES) * STAGE_BYTES;
        const uint32_t sAh = stage, sAl = stage + 16384;
        const uint32_t sWh = stage + 32768, sWl = stage + 49152;

#pragma unroll
        for (int ks = 0; ks < 4; ks++) {
            const int kc = ks * 16;
            uint32_t ah[4][4], al[4][4];
#pragma unroll
            for (int fm = 0; fm < 4; fm++) {
                const uint32_t off = SWZ((uint32_t)((aRow + fm * 16) * 128 + (kc + aColSel) * 2));
                ldsm4(ah[fm], sAh + off);
                ldsm4(al[fm], sAl + off);
            }
#pragma unroll
            for (int ng = 0; ng < 4; ng++) {
                const uint32_t off = SWZ((uint32_t)((bRow + ng * 16) * 128 + (kc + bColSel) * 2));
                uint32_t t[4], u[4];
                ldsm4(t, sWh + off);
                ldsm4(u, sWl + off);
                uint32_t bh0[2] = { t[0], t[1] }, bh1[2] = { t[2], t[3] };
                uint32_t bl0[2] = { u[0], u[1] }, bl1[2] = { u[2], u[3] };
#pragma unroll
                for (int fm = 0; fm < 4; fm++) {
                    mma16816(acc[fm][ng*2],   ah[fm], bh0);
                    mma16816(acc[fm][ng*2],   ah[fm], bl0);
                    mma16816(acc[fm][ng*2],   al[fm], bh0);
                    mma16816(acc[fm][ng*2+1], ah[fm], bh1);
                    mma16816(acc[fm][ng*2+1], ah[fm], bl1);
                    mma16816(acc[fm][ng*2+1], al[fm], bh1);
                }
            }
        }
        __syncthreads();

        if (c + 2 < NC) {
            load_stage((c + 2) % GEMM_STAGES, (c + 2) * 64);
            CP_COMMIT();
        }
    }

    // ---- epilogue: regs -> gmem with bias / gelu / bf16 hi-lo split ----
    const int erow = mBase + wm * 64 + (lane >> 2);
    const int ecol = nBase + wn * 64 + (lane & 3) * 2;
#pragma unroll
    for (int fm = 0; fm < 4; fm++) {
#pragma unroll
        for (int fn = 0; fn < 8; fn++) {
            const int col = ecol + fn * 8;
#pragma unroll
            for (int half = 0; half < 2; half++) {
                const int row = erow + fm * 16 + half * 8;
                float v0 = acc[fm][fn][half * 2 + 0];
                float v1 = acc[fm][fn][half * 2 + 1];
                if (bias) { v0 += bias[col]; v1 += bias[col + 1]; }
                if (ACT == 1) {
                    v0 = 0.5f * v0 * (1.f + erff(v0 * 0.70710678118654752f));
                    v1 = 0.5f * v1 * (1.f + erff(v1 * 0.70710678118654752f));
                }
                const size_t base = (size_t)row * Nn + col;
                if (OUTBF16) {
                    uint32_t hp, lp;
                    pack_hl(v0, v1, hp, lp);
                    *(uint32_t*)(Ch + base) = hp;
                    *(uint32_t*)(Cl + base) = lp;
                } else {
                    *(float2*)(Cf + base) = make_float2(v0, v1);
                }
            }
        }
    }
}

template <int ACT, int OUTBF16>
__global__ __launch_bounds__(GEMM_THREADS, 1)
void mma_gemm(const __nv_bfloat16* __restrict__ Ah, const __nv_bfloat16* __restrict__ Al,
              const __nv_bfloat16* __restrict__ Wh, const __nv_bfloat16* __restrict__ Wl,
              const float* __restrict__ bias,
              float* __restrict__ Cf,
              __nv_bfloat16* __restrict__ Ch, __nv_bfloat16* __restrict__ Cl,
              int Nn, int K) {
    extern __shared__ char dsm[];
    gemm_body<ACT, OUTBF16>(Ah, Al, Wh, Wl, bias, Cf, Ch, Cl,
                            Nn, K, blockIdx.y * 128, blockIdx.x * 128, dsm);
}

// fused QKV: gridDim.z selects which projection this CTA computes
__global__ __launch_bounds__(GEMM_THREADS, 1)
void qkv_gemm(const __nv_bfloat16* __restrict__ Ah, const __nv_bfloat16* __restrict__ Al,
              const __nv_bfloat16* __restrict__ Wqh, const __nv_bfloat16* __restrict__ Wql,
              const __nv_bfloat16* __restrict__ Wkh, const __nv_bfloat16* __restrict__ Wkl,
              const __nv_bfloat16* __restrict__ Wvh, const __nv_bfloat16* __restrict__ Wvl,
              __nv_bfloat16* __restrict__ Cqh, __nv_bfloat16* __restrict__ Cql,
              __nv_bfloat16* __restrict__ Ckh, __nv_bfloat16* __restrict__ Ckl,
              __nv_bfloat16* __restrict__ Cvh, __nv_bfloat16* __restrict__ Cvl) {
    extern __shared__ char dsm[];
    const int z = blockIdx.z;
    const __nv_bfloat16* Wh = (z == 0) ? Wqh : (z == 1) ? Wkh : Wvh;
    const __nv_bfloat16* Wl = (z == 0) ? Wql : (z == 1) ? Wkl : Wvl;
    __nv_bfloat16* Ch = (z == 0) ? Cqh : (z == 1) ? Ckh : Cvh;
    __nv_bfloat16* Cl = (z == 0) ? Cql : (z == 1) ? Ckl : Cvl;
    gemm_body<0, 1>(Ah, Al, Wh, Wl, nullptr, nullptr, Ch, Cl,
                    D_, D_, blockIdx.y * 128, blockIdx.x * 128, dsm);
}

// ---------------- flash attention with mma.sync (3-term bf16 splits) ----------------
// CTA = (b, h, 128-query tile). 8 warps x 16 rows. KV tiles of 64 keys, double-buf.
#define ATT_STAGE 33792
#define ATT_SMEM  (32768 + 2 * ATT_STAGE)

__global__ __launch_bounds__(256, 1)
void attn_mma_kernel(const __nv_bfloat16* __restrict__ qh, const __nv_bfloat16* __restrict__ ql,
                     const __nv_bfloat16* __restrict__ kh, const __nv_bfloat16* __restrict__ kl,
                     const __nv_bfloat16* __restrict__ vh, const __nv_bfloat16* __restrict__ vl,
                     const int* __restrict__ coords,
                     __nv_bfloat16* __restrict__ aoh, __nv_bfloat16* __restrict__ aol) {
    extern __shared__ char dsm[];
    const uint32_t sb = s2u(dsm);

    const int tid  = threadIdx.x;
    const int wid  = tid >> 5;
    const int lane = tid & 31;
    const int qt = blockIdx.x & 7;
    const int h  = (blockIdx.x >> 3) & 15;
    const int b  = blockIdx.x >> 7;
    const int qbase = qt * 128;

    const float slope = exp2f(-0.5f * (float)(h + 1));
    const float scale = 0.125f;

    const int r0 = wid * 16 + (lane >> 2);
    const int grow0 = b * N_ + qbase + r0;
    const float xi0 = (float)coords[grow0 * 2 + 0];
    const float yi0 = (float)coords[grow0 * 2 + 1];
    const float xi1 = (float)coords[(grow0 + 8) * 2 + 0];
    const float yi1 = (float)coords[(grow0 + 8) * 2 + 1];

    {
        const int rr = tid >> 3, cc = tid & 7;
#pragma unroll
        for (int j = 0; j < 4; j++) {
            const int r = rr + 32 * j;
            const size_t go = (size_t)(b * N_ + qbase + r) * D_ + h * HD_ + cc * 8;
            const uint32_t off = SWZ((uint32_t)(r * 128 + cc * 16));
            cp_async16(sb + off, qh + go);
            cp_async16(sb + 16384 + off, ql + go);
        }
    }
    CP_COMMIT();

    auto load_kv = [&](int t, int buf) {
        const uint32_t st = sb + 32768 + buf * ATT_STAGE;
        const int kt = t * 64;
        const int rr = tid >> 2, cc = tid & 3;
        const size_t gbase = (size_t)(b * N_ + kt) * D_ + h * HD_;
        const __nv_bfloat16* G[4] = { kh + gbase, kl + gbase, vh + gbase, vl + gbase };
#pragma unroll
        for (int m = 0; m < 4; m++) {
#pragma unroll
            for (int j = 0; j < 2; j++) {
                const int ch = cc + 4 * j;
                cp_async16(st + m * 8192 + SWZ((uint32_t)(rr * 128 + ch * 16)),
                           G[m] + (size_t)rr * D_ + ch * 8);
            }
        }
        if (tid < 32)
            cp_async16(st + 32768 + tid * 16,
                       (const char*)coords + (size_t)(b * N_ + kt) * 8 + tid * 16);
    };

    load_kv(0, 0);
    CP_COMMIT();

    float m0 = -1e30f, m1 = -1e30f, l0 = 0.f, l1 = 0.f;
    float acc_o[8][4];
#pragma unroll
    for (int f = 0; f < 8; f++)
#pragma unroll
        for (int t = 0; t < 4; t++) acc_o[f][t] = 0.f;

    const int aRow  = wid * 16 + (lane & 15);
    const int aCol  = (lane >> 4) * 8;
    const int bRowK = ((lane >> 4) << 3) + (lane & 7);
    const int bColK = ((lane >> 3) & 1) * 8;
    const int vRow  = ((lane >> 3) & 1) * 8 + (lane & 7);
    const int vCol  = (lane >> 4) * 8;

    for (int t = 0; t < 16; t++) {
        const int buf = t & 1;
        if (t + 1 < 16) { load_kv(t + 1, 1 - buf); CP_COMMIT(); CP_WAIT(1); }
        else            { CP_WAIT(0); }
        __syncthreads();

        const uint32_t st = sb + 32768 + buf * ATT_STAGE;
        const uint32_t sKh = st, sKl = st + 8192, sVh = st + 16384, sVl = st + 24576;
        const int2* kco = (const int2*)(dsm + 32768 + buf * ATT_STAGE + 32768);

        float accs[8][4];
#pragma unroll
        for (int f = 0; f < 8; f++)
#pragma unroll
            for (int u = 0; u < 4; u++) accs[f][u] = 0.f;

#pragma unroll
        for (int ks = 0; ks < 4; ks++) {
            const int kc = ks * 16;
            uint32_t ah[4], al[4];
            const uint32_t aoff = SWZ((uint32_t)(aRow * 128 + (kc + aCol) * 2));
            ldsm4(ah, sb + aoff);
            ldsm4(al, sb + 16384 + aoff);
#pragma unroll
            for (int nh = 0; nh < 4; nh++) {
                const uint32_t boff = SWZ((uint32_t)((nh * 16 + bRowK) * 128 + (kc + bColK) * 2));
                uint32_t tb[4], tl[4];
                ldsm4(tb, sKh + boff);
                ldsm4(tl, sKl + boff);
                uint32_t bh0[2] = { tb[0], tb[1] }, bh1[2] = { tb[2], tb[3] };
                uint32_t bl0[2] = { tl[0], tl[1] }, bl1[2] = { tl[2], tl[3] };
                mma16816(accs[nh*2],   ah, bh0);
                mma16816(accs[nh*2],   ah, bl0);
                mma16816(accs[nh*2],   al, bh0);
                mma16816(accs[nh*2+1], ah, bh1);
                mma16816(accs[nh*2+1], ah, bl1);
                mma16816(accs[nh*2+1], al, bh1);
            }
        }

#pragma unroll
        for (int f = 0; f < 8; f++) {
            const int c = f * 8 + (lane & 3) * 2;
            const int2 ca = kco[c], cb = kco[c + 1];
            const float xa = (float)ca.x, ya = (float)ca.y;
            const float xb = (float)cb.x, yb = (float)cb.y;
            accs[f][0] = fmaf(accs[f][0], scale, slope * (fabsf(xi0 - xa) + fabsf(yi0 - ya)));
            accs[f][1] = fmaf(accs[f][1], scale, slope * (fabsf(xi0 - xb) + fabsf(yi0 - yb)));
            accs[f][2] = fmaf(accs[f][2], scale, slope * (fabsf(xi1 - xa) + fabsf(yi1 - ya)));
            accs[f][3] = fmaf(accs[f][3], scale, slope * (fabsf(xi1 - xb) + fabsf(yi1 - yb)));
        }

        float mx0 = -1e30f, mx1 = -1e30f;
#pragma unroll
        for (int f = 0; f < 8; f++) {
            mx0 = fmaxf(mx0, fmaxf(accs[f][0], accs[f][1]));
            mx1 = fmaxf(mx1, fmaxf(accs[f][2], accs[f][3]));
        }
        mx0 = fmaxf(mx0, __shfl_xor_sync(0xffffffffu, mx0, 1));
        mx0 = fmaxf(mx0, __shfl_xor_sync(0xffffffffu, mx0, 2));
        mx1 = fmaxf(mx1, __shfl_xor_sync(0xffffffffu, mx1, 1));
        mx1 = fmaxf(mx1, __shfl_xor_sync(0xffffffffu, mx1, 2));
        const float nm0 = fmaxf(m0, mx0), nm1 = fmaxf(m1, mx1);
        const float cr0 = __expf(m0 - nm0), cr1 = __expf(m1 - nm1);
        m0 = nm0; m1 = nm1;
        l0 *= cr0; l1 *= cr1;
#pragma unroll
        for (int f = 0; f < 8; f++) {
            acc_o[f][0] *= cr0; acc_o[f][1] *= cr0;
            acc_o[f][2] *= cr1; acc_o[f][3] *= cr1;
        }
#pragma unroll
        for (int f = 0; f < 8; f++) {
            accs[f][0] = __expf(accs[f][0] - nm0);
            accs[f][1] = __expf(accs[f][1] - nm0);
            accs[f][2] = __expf(accs[f][2] - nm1);
            accs[f][3] = __expf(accs[f][3] - nm1);
            l0 += accs[f][0] + accs[f][1];
            l1 += accs[f][2] + accs[f][3];
        }

#pragma unroll
        for (int kg = 0; kg < 4; kg++) {
            const float* s0 = accs[2 * kg];
            const float* s1 = accs[2 * kg + 1];
            uint32_t pah[4], pal[4];
            pack_hl(s0[0], s0[1], pah[0], pal[0]);
            pack_hl(s0[2], s0[3], pah[1], pal[1]);
            pack_hl(s1[0], s1[1], pah[2], pal[2]);
            pack_hl(s1[2], s1[3], pah[3], pal[3]);
#pragma unroll
            for (int vi = 0; vi < 4; vi++) {
                const uint32_t voff =
                    SWZ((uint32_t)((kg * 16 + vRow) * 128 + (vi * 16 + vCol) * 2));
                uint32_t tv[4], tw[4];
                ldsm4t(tv, sVh + voff);
                ldsm4t(tw, sVl + voff);
                uint32_t bvh0[2] = { tv[0], tv[1] }, bvh1[2] = { tv[2], tv[3] };
                uint32_t bvl0[2] = { tw[0], tw[1] }, bvl1[2] = { tw[2], tw[3] };
                mma16816(acc_o[vi*2],   pah, bvh0);
                mma16816(acc_o[vi*2],   pah, bvl0);
                mma16816(acc_o[vi*2],   pal, bvh0);
                mma16816(acc_o[vi*2+1], pah, bvh1);
                mma16816(acc_o[vi*2+1], pah, bvl1);
                mma16816(acc_o[vi*2+1], pal, bvh1);
            }
        }
        __syncthreads();
    }

    l0 += __shfl_xor_sync(0xffffffffu, l0, 1);
    l0 += __shfl_xor_sync(0xffffffffu, l0, 2);
    l1 += __shfl_xor_sync(0xffffffffu, l1, 1);
    l1 += __shfl_xor_sync(0xffffffffu, l1, 2);
    const float inv0 = 1.f / l0, inv1 = 1.f / l1;
#pragma unroll
    for (int f = 0; f < 8; f++) {
        const int c = f * 8 + (lane & 3) * 2;
        const size_t base0 = (size_t)grow0 * D_ + h * HD_ + c;
        const size_t base1 = (size_t)(grow0 + 8) * D_ + h * HD_ + c;
        uint32_t hp, lp;
        pack_hl(acc_o[f][0] * inv0, acc_o[f][1] * inv0, hp, lp);
        *(uint32_t*)(aoh + base0) = hp;
        *(uint32_t*)(aol + base0) = lp;
        pack_hl(acc_o[f][2] * inv1, acc_o[f][3] * inv1, hp, lp);
        *(uint32_t*)(aoh + base1) = hp;
        *(uint32_t*)(aol + base1) = lp;
    }
}

// ---------------- fused residual add + LayerNorm (+ optional bf16 hi/lo emit) -------
__global__ __launch_bounds__(256)
void add_ln_kernel(const float* __restrict__ a, const float* __restrict__ bsum,
                   const float* __restrict__ g, const float* __restrict__ be,
                   float* __restrict__ out,
                   __nv_bfloat16* __restrict__ hi, __nv_bfloat16* __restrict__ lo) {
    const int row = blockIdx.x;
    const int tid = threadIdx.x;
    const float* pa = a    + (size_t)row * D_;
    const float* pb = bsum + (size_t)row * D_;

    float v[4];
    float s = 0.f, ss = 0.f;
#pragma unroll
    for (int i = 0; i < 4; i++) {
        const int c = tid + 256 * i;
        const float t = pa[c] + pb[c];
        v[i] = t; s += t; ss = fmaf(t, t, ss);
    }
#pragma unroll
    for (int o = 16; o > 0; o >>= 1) {
        s  += __shfl_xor_sync(0xffffffffu, s,  o);
        ss += __shfl_xor_sync(0xffffffffu, ss, o);
    }
    __shared__ float rs[8], rss[8];
    __shared__ float smu, sinv;
    const int w = tid >> 5;
    if ((tid & 31) == 0) { rs[w] = s; rss[w] = ss; }
    __syncthreads();
    if (tid == 0) {
        float S = 0.f, SS = 0.f;
#pragma unroll
        for (int i = 0; i < 8; i++) { S += rs[i]; SS += rss[i]; }
        const float mu  = S * (1.f / 1024.f);
        const float var = SS * (1.f / 1024.f) - mu * mu;
        smu = mu; sinv = rsqrtf(var + 1e-5f);
    }
    __syncthreads();
    const float mu = smu, inv = sinv;
#pragma unroll
    for (int i = 0; i < 4; i++) {
        const int c = tid + 256 * i;
        const float o = (v[i] - mu) * inv * g[c] + be[c];
        out[(size_t)row * D_ + c] = o;
        if (hi) {
            const __nv_bfloat16 hh = __float2bfloat16(o);
            hi[(size_t)row * D_ + c] = hh;
            lo[(size_t)row * D_ + c] = __float2bfloat16(o - __bfloat162float(hh));
        }
    }
}

// ---------------- launch ----------------
extern "C" void kernel_launch(void* const* d_in, const int* in_sizes, int n_in,
                              void* d_out, int out_size) {
    const float* src    = (const float*)d_in[0];
    const int*   coords = (const int*)  d_in[1];
    const float* Wq = (const float*)d_in[2];
    const float* Wk = (const float*)d_in[3];
    const float* Wv = (const float*)d_in[4];
    const float* Wo = (const float*)d_in[5];
    const float* W1 = (const float*)d_in[6];
    const float* b1 = (const float*)d_in[7];
    const float* W2 = (const float*)d_in[8];
    const float* b2 = (const float*)d_in[9];
    const float* g1 = (const float*)d_in[10];
    const float* be1= (const float*)d_in[11];
    const float* g2 = (const float*)d_in[12];
    const float* be2= (const float*)d_in[13];
    float* out = (float*)d_out;

    void *pt, *px;
    cudaGetSymbolAddress(&pt, g_t);
    cudaGetSymbolAddress(&px, g_x);

    void *srch,*srcl,*wqh,*wql,*wkh,*wkl,*wvh,*wvl,*woh,*wol,*w1h,*w1l,*w2h,*w2l;
    void *xh,*xl,*aoh,*aol,*ffh,*ffl,*qhh,*qll,*khh,*kll,*vhh,*vll;
    cudaGetSymbolAddress(&srch, s_src_h); cudaGetSymbolAddress(&srcl, s_src_l);
    cudaGetSymbolAddress(&wqh, s_wq_h);   cudaGetSymbolAddress(&wql, s_wq_l);
    cudaGetSymbolAddress(&wkh, s_wk_h);   cudaGetSymbolAddress(&wkl, s_wk_l);
    cudaGetSymbolAddress(&wvh, s_wv_h);   cudaGetSymbolAddress(&wvl, s_wv_l);
    cudaGetSymbolAddress(&woh, s_wo_h);   cudaGetSymbolAddress(&wol, s_wo_l);
    cudaGetSymbolAddress(&w1h, s_w1_h);   cudaGetSymbolAddress(&w1l, s_w1_l);
    cudaGetSymbolAddress(&w2h, s_w2_h);   cudaGetSymbolAddress(&w2l, s_w2_l);
    cudaGetSymbolAddress(&xh,  s_x_h);    cudaGetSymbolAddress(&xl,  s_x_l);
    cudaGetSymbolAddress(&aoh, s_ao_h);   cudaGetSymbolAddress(&aol, s_ao_l);
    cudaGetSymbolAddress(&ffh, s_ff_h);   cudaGetSymbolAddress(&ffl, s_ff_l);
    cudaGetSymbolAddress(&qhh, s_q_h);    cudaGetSymbolAddress(&qll, s_q_l);
    cudaGetSymbolAddress(&khh, s_k_h);    cudaGetSymbolAddress(&kll, s_k_l);
    cudaGetSymbolAddress(&vhh, s_v_h);    cudaGetSymbolAddress(&vll, s_v_l);

    cudaFuncSetAttribute((const void*)mma_gemm<0, 0>,
                         cudaFuncAttributeMaxDynamicSharedMemorySize, GEMM_SMEM_BYTES);
    cudaFuncSetAttribute((const void*)mma_gemm<0, 1>,
                         cudaFuncAttributeMaxDynamicSharedMemorySize, GEMM_SMEM_BYTES);
    cudaFuncSetAttribute((const void*)mma_gemm<1, 1>,
                         cudaFuncAttributeMaxDynamicSharedMemorySize, GEMM_SMEM_BYTES);
    cudaFuncSetAttribute((const void*)qkv_gemm,
                         cudaFuncAttributeMaxDynamicSharedMemorySize, GEMM_SMEM_BYTES);
    cudaFuncSetAttribute((const void*)attn_mma_kernel,
                         cudaFuncAttributeMaxDynamicSharedMemorySize, ATT_SMEM);

    const int nSrc4 = M_ * D_ / 4;
    const int nW4   = D_ * D_ / 4;
    const int nW14  = FF_ * D_ / 4;

    const dim3 gblk(GEMM_THREADS);
    const dim3 gD(D_ / 128, M_ / 128);        // (8, 32)
    const dim3 gQKV(D_ / 128, M_ / 128, 3);   // (8, 32, 3)
    const dim3 gF(FF_ / 128, M_ / 128);       // (32, 32)

    // splits needed for QKV
    split_kernel<<<nSrc4 / 256, 256>>>((const float4*)src, (uint2*)srch, (uint2*)srcl, nSrc4);
    split_kernel<<<nW4 / 256, 256>>>((const float4*)Wq, (uint2*)wqh, (uint2*)wql, nW4);
    split_kernel<<<nW4 / 256, 256>>>((const float4*)Wk, (uint2*)wkh, (uint2*)wkl, nW4);
    split_kernel<<<nW4 / 256, 256>>>((const float4*)Wv, (uint2*)wvh, (uint2*)wvl, nW4);

    // fused QKV projections (one launch, gridDim.z selects q/k/v)
    qkv_gemm<<<gQKV, gblk, GEMM_SMEM_BYTES>>>(
        (const __nv_bfloat16*)srch, (const __nv_bfloat16*)srcl,
        (const __nv_bfloat16*)wqh,  (const __nv_bfloat16*)wql,
        (const __nv_bfloat16*)wkh,  (const __nv_bfloat16*)wkl,
        (const __nv_bfloat16*)wvh,  (const __nv_bfloat16*)wvl,
        (__nv_bfloat16*)qhh, (__nv_bfloat16*)qll,
        (__nv_bfloat16*)khh, (__nv_bfloat16*)kll,
        (__nv_bfloat16*)vhh, (__nv_bfloat16*)vll);

    // remaining weight splits
    split_kernel<<<nW4 / 256, 256>>>((const float4*)Wo, (uint2*)woh, (uint2*)wol, nW4);
    split_kernel<<<nW14 / 256, 256>>>((const float4*)W1, (uint2*)w1h, (uint2*)w1l, nW14);
    split_kernel<<<nW14 / 256, 256>>>((const float4*)W2, (uint2*)w2h, (uint2*)w2l, nW14);

    // flash attention (tensor cores, bf16 hi/lo in and out)
    attn_mma_kernel<<<512, 256, ATT_SMEM>>>(
        (const __nv_bfloat16*)qhh, (const __nv_bfloat16*)qll,
        (const __nv_bfloat16*)khh, (const __nv_bfloat16*)kll,
        (const __nv_bfloat16*)vhh, (const __nv_bfloat16*)vll,
        coords, (__nv_bfloat16*)aoh, (__nv_bfloat16*)aol);

    // output projection -> fp32 t ; residual + LN1 -> x (fp32 + bf16 hi/lo)
    mma_gemm<0, 0><<<gD, gblk, GEMM_SMEM_BYTES>>>(
        (const __nv_bfloat16*)aoh, (const __nv_bfloat16*)aol,
        (const __nv_bfloat16*)woh, (const __nv_bfloat16*)wol,
        nullptr, (float*)pt, nullptr, nullptr, D_, D_);
    add_ln_kernel<<<M_, 256>>>(src, (const float*)pt, g1, be1, (float*)px,
                               (__nv_bfloat16*)xh, (__nv_bfloat16*)xl);

    // FFN1 (bias + exact gelu, bf16 hi/lo output)
    mma_gemm<1, 1><<<gF, gblk, GEMM_SMEM_BYTES>>>(
        (const __nv_bfloat16*)xh,  (const __nv_bfloat16*)xl,
        (const __nv_bfloat16*)w1h, (const __nv_bfloat16*)w1l,
        b1, nullptr, (__nv_bfloat16*)ffh, (__nv_bfloat16*)ffl, FF_, D_);

    // FFN2 (bias, fp32 output) ; residual + LN2 -> out
    mma_gemm<0, 0><<<gD, gblk, GEMM_SMEM_BYTES>>>(
        (const __nv_bfloat16*)ffh, (const __nv_bfloat16*)ffl,
        (const __nv_bfloat16*)w2h, (const __nv_bfloat16*)w2l,
        b2, (float*)pt, nullptr, nullptr, D_, FF_);
    add_ln_kernel<<<M_, 256>>>((const float*)px, (const float*)pt, g2, be2, out,
                               nullptr, nullptr);
}

// round 9
// speedup vs baseline: 1.2219x; 1.2219x over previous
#include <cuda_runtime.h>
#include <cuda_fp16.h>
#include <math.h>
#include <stdint.h>

#define B_   4
#define N_   1024
#define D_   1024
#define H_   16
#define HD_  64
#define FF_  4096
#define M_   (B_ * N_)   // 4096 rows

// ---------------- scratch (static device globals; no allocs allowed) ----------------
__device__ float g_t [M_ * D_];   // src2 / ffn2 output temp (fp32)
__device__ float g_x [M_ * D_];   // post-LN1 activations (fp32)

// fp16 hi/lo split buffers
__device__ __half s_src_h[M_ * D_],  s_src_l[M_ * D_];
__device__ __half s_wq_h [D_ * D_],  s_wq_l [D_ * D_];
__device__ __half s_wk_h [D_ * D_],  s_wk_l [D_ * D_];
__device__ __half s_wv_h [D_ * D_],  s_wv_l [D_ * D_];
__device__ __half s_wo_h [D_ * D_],  s_wo_l [D_ * D_];
__device__ __half s_w1_h [FF_ * D_], s_w1_l [FF_ * D_];
__device__ __half s_w2_h [D_ * FF_], s_w2_l [D_ * FF_];
__device__ __half s_x_h  [M_ * D_];                      // plain fp16 (FFN1 2-term)
__device__ __half s_ao_h [M_ * D_],  s_ao_l [M_ * D_];
__device__ __half s_ff_h [M_ * FF_];                     // plain fp16 (FFN2 2-term)
__device__ __half s_q_h  [M_ * D_],  s_q_l  [M_ * D_];
__device__ __half s_k_h  [M_ * D_],  s_k_l  [M_ * D_];
__device__ __half s_v_h  [M_ * D_],  s_v_l  [M_ * D_];

// ---------------- PTX helpers (Ampere-era only: valid at compute_103 base) ----------
__device__ __forceinline__ uint32_t s2u(const void* p) {
    uint32_t a;
    asm("{ .reg .u64 t; cvta.to.shared.u64 t, %1; cvt.u32.u64 %0, t; }" : "=r"(a) : "l"(p));
    return a;
}
__device__ __forceinline__ void cp_async16(uint32_t saddr, const void* g) {
    asm volatile("cp.async.cg.shared.global [%0], [%1], 16;" :: "r"(saddr), "l"(g) : "memory");
}
#define CP_COMMIT()  asm volatile("cp.async.commit_group;" ::: "memory")
#define CP_WAIT(n)   asm volatile("cp.async.wait_group %0;" :: "n"(n) : "memory")

__device__ __forceinline__ void ldsm4(uint32_t* r, uint32_t addr) {
    asm volatile("ldmatrix.sync.aligned.m8n8.x4.shared.b16 {%0,%1,%2,%3}, [%4];"
                 : "=r"(r[0]), "=r"(r[1]), "=r"(r[2]), "=r"(r[3]) : "r"(addr));
}
__device__ __forceinline__ void ldsm4t(uint32_t* r, uint32_t addr) {
    asm volatile("ldmatrix.sync.aligned.m8n8.x4.trans.shared.b16 {%0,%1,%2,%3}, [%4];"
                 : "=r"(r[0]), "=r"(r[1]), "=r"(r[2]), "=r"(r[3]) : "r"(addr));
}
__device__ __forceinline__ void mma16816(float* c, const uint32_t* a, const uint32_t* b) {
    asm volatile(
        "mma.sync.aligned.m16n8k16.row.col.f32.f16.f16.f32 "
        "{%0,%1,%2,%3}, {%4,%5,%6,%7}, {%8,%9}, {%0,%1,%2,%3};"
        : "+f"(c[0]), "+f"(c[1]), "+f"(c[2]), "+f"(c[3])
        : "r"(a[0]), "r"(a[1]), "r"(a[2]), "r"(a[3]), "r"(b[0]), "r"(b[1]));
}

#define SWZ(o) ((o) ^ (((o) >> 3) & 0x70))

__device__ __forceinline__ void pack_hl(float a, float b, uint32_t& hi, uint32_t& lo) {
    __half ha = __float2half_rn(a), hb = __float2half_rn(b);
    __half2 hp = __halves2half2(ha, hb);
    hi = *(uint32_t*)&hp;
    __half2 lp = __halves2half2(
        __float2half_rn(a - __half2float(ha)),
        __float2half_rn(b - __half2float(hb)));
    lo = *(uint32_t*)&lp;
}
__device__ __forceinline__ uint32_t pack_h(float a, float b) {
    __half2 hp = __halves2half2(__float2half_rn(a), __float2half_rn(b));
    return *(uint32_t*)&hp;
}

// ---------------- split fp32 -> fp16 (hi, lo) ----------------
__global__ __launch_bounds__(256)
void split_kernel(const float4* __restrict__ x, uint2* __restrict__ hi,
                  uint2* __restrict__ lo, int n4) {
    int i = blockIdx.x * 256 + threadIdx.x;
    if (i >= n4) return;
    float4 v = x[i];
    uint32_t h0, l0, h1, l1;
    pack_hl(v.x, v.y, h0, l0);
    pack_hl(v.z, v.w, h1, l1);
    hi[i] = make_uint2(h0, h1);
    lo[i] = make_uint2(l0, l1);
}

// ---------------- HMMA GEMM body: 128x128 tile, 256 thr, warptile 64x32 ------------
// BK=64, 2-stage cp.async. stage: Ah[0,16K) Al[16K,32K) Wh[32K,48K) Wl[48K,64K)
// TERMS==3: AhWh + AhWl + AlWh (A and W both split)
// TERMS==2: AhWh + AhWl       (A plain fp16, W split; Al slot unused/unloaded)
// OUTMODE: 0 = fp32, 1 = fp16 hi+lo, 2 = fp16 hi only
#define STAGE_BYTES 65536
#define GEMM_SMEM_BYTES (2 * STAGE_BYTES)

template <int ACT, int OUTMODE, int TERMS>
__device__ __forceinline__
void gemm_body(const __half* __restrict__ Ah, const __half* __restrict__ Al,
               const __half* __restrict__ Wh, const __half* __restrict__ Wl,
               const float* __restrict__ bias,
               float* __restrict__ Cf,
               __half* __restrict__ Ch, __half* __restrict__ Cl,
               int Nn, int K, int mBase, int nBase, char* dsm) {
    const uint32_t sb = s2u(dsm);

    const int tid  = threadIdx.x;
    const int wid  = tid >> 5;
    const int lane = tid & 31;
    const int wm   = wid & 1;        // 2 warps in m (64 rows each)
    const int wn   = wid >> 1;       // 4 warps in n (32 cols each)
    const int NC = K / 64;

    const int r0 = tid >> 3;
    const int c0 = tid & 7;

    const __half* pAh = Ah + (size_t)(mBase + r0) * K + c0 * 8;
    const __half* pAl = (TERMS == 3) ? Al + (size_t)(mBase + r0) * K + c0 * 8 : nullptr;
    const __half* pWh = Wh + (size_t)(nBase + r0) * K + c0 * 8;
    const __half* pWl = Wl + (size_t)(nBase + r0) * K + c0 * 8;

    auto load_stage = [&](int buf, int kcol) {
        const uint32_t stage = sb + buf * STAGE_BYTES;
#pragma unroll
        for (int j = 0; j < 4; j++) {
            const int r = r0 + 32 * j;
            const uint32_t off = SWZ((uint32_t)(r * 128 + c0 * 16));
            cp_async16(stage + off,         pAh + (size_t)(32 * j) * K + kcol);
            if (TERMS == 3)
                cp_async16(stage + 16384 + off, pAl + (size_t)(32 * j) * K + kcol);
            cp_async16(stage + 32768 + off, pWh + (size_t)(32 * j) * K + kcol);
            cp_async16(stage + 49152 + off, pWl + (size_t)(32 * j) * K + kcol);
        }
    };

    float acc[4][4][4];
#pragma unroll
    for (int i = 0; i < 4; i++)
#pragma unroll
        for (int j = 0; j < 4; j++)
#pragma unroll
            for (int t = 0; t < 4; t++) acc[i][j][t] = 0.f;

    const int aRow = wm * 64 + (lane & 15);
    const int aColSel = (lane >> 4) * 8;
    const int bRow = wn * 32 + ((lane >> 4) << 3) + (lane & 7);
    const int bColSel = ((lane >> 3) & 1) * 8;

    load_stage(0, 0);
    CP_COMMIT();

    for (int c = 0; c < NC; c++) {
        if (c + 1 < NC) {
            load_stage((c + 1) & 1, (c + 1) * 64);
            CP_COMMIT();
            CP_WAIT(1);
        } else {
            CP_WAIT(0);
        }
        __syncthreads();

        const uint32_t stage = sb + (c & 1) * STAGE_BYTES;
        const uint32_t sAh = stage, sAl = stage + 16384;
        const uint32_t sWh = stage + 32768, sWl = stage + 49152;

#pragma unroll
        for (int ks = 0; ks < 4; ks++) {
            const int kc = ks * 16;
            uint32_t ah[4][4], al[4][4];
#pragma unroll
            for (int fm = 0; fm < 4; fm++) {
                const uint32_t off = SWZ((uint32_t)((aRow + fm * 16) * 128 + (kc + aColSel) * 2));
                ldsm4(ah[fm], sAh + off);
                if (TERMS == 3) ldsm4(al[fm], sAl + off);
            }
            uint32_t bh[4][2], bl[4][2];
#pragma unroll
            for (int ng = 0; ng < 2; ng++) {
                const uint32_t off = SWZ((uint32_t)((bRow + ng * 16) * 128 + (kc + bColSel) * 2));
                uint32_t t[4];
                ldsm4(t, sWh + off);
                bh[ng*2][0] = t[0]; bh[ng*2][1] = t[1];
                bh[ng*2+1][0] = t[2]; bh[ng*2+1][1] = t[3];
                ldsm4(t, sWl + off);
                bl[ng*2][0] = t[0]; bl[ng*2][1] = t[1];
                bl[ng*2+1][0] = t[2]; bl[ng*2+1][1] = t[3];
            }
#pragma unroll
            for (int fm = 0; fm < 4; fm++)
#pragma unroll
                for (int fn = 0; fn < 4; fn++) {
                    mma16816(acc[fm][fn], ah[fm], bh[fn]);
                    mma16816(acc[fm][fn], ah[fm], bl[fn]);
                    if (TERMS == 3) mma16816(acc[fm][fn], al[fm], bh[fn]);
                }
        }
        __syncthreads();
    }

    // ---- epilogue ----
    const int erow = mBase + wm * 64 + (lane >> 2);
    const int ecol = nBase + wn * 32 + (lane & 3) * 2;
#pragma unroll
    for (int fm = 0; fm < 4; fm++) {
#pragma unroll
        for (int fn = 0; fn < 4; fn++) {
            const int col = ecol + fn * 8;
#pragma unroll
            for (int half = 0; half < 2; half++) {
                const int row = erow + fm * 16 + half * 8;
                float v0 = acc[fm][fn][half * 2 + 0];
                float v1 = acc[fm][fn][half * 2 + 1];
                if (bias) { v0 += bias[col]; v1 += bias[col + 1]; }
                if (ACT == 1) {
                    v0 = 0.5f * v0 * (1.f + erff(v0 * 0.70710678118654752f));
                    v1 = 0.5f * v1 * (1.f + erff(v1 * 0.70710678118654752f));
                }
                const size_t base = (size_t)row * Nn + col;
                if (OUTMODE == 1) {
                    uint32_t hp, lp;
                    pack_hl(v0, v1, hp, lp);
                    *(uint32_t*)(Ch + base) = hp;
                    *(uint32_t*)(Cl + base) = lp;
                } else if (OUTMODE == 2) {
                    *(uint32_t*)(Ch + base) = pack_h(v0, v1);
                } else {
                    *(float2*)(Cf + base) = make_float2(v0, v1);
                }
            }
        }
    }
}

template <int ACT, int OUTMODE, int TERMS>
__global__ __launch_bounds__(256, 1)
void mma_gemm(const __half* __restrict__ Ah, const __half* __restrict__ Al,
              const __half* __restrict__ Wh, const __half* __restrict__ Wl,
              const float* __restrict__ bias,
              float* __restrict__ Cf,
              __half* __restrict__ Ch, __half* __restrict__ Cl,
              int Nn, int K) {
    extern __shared__ char dsm[];
    gemm_body<ACT, OUTMODE, TERMS>(Ah, Al, Wh, Wl, bias, Cf, Ch, Cl,
                                   Nn, K, blockIdx.y * 128, blockIdx.x * 128, dsm);
}

// fused QKV: gridDim.z selects which projection this CTA computes (3-term)
__global__ __launch_bounds__(256, 1)
void qkv_gemm(const __half* __restrict__ Ah, const __half* __restrict__ Al,
              const __half* __restrict__ Wqh, const __half* __restrict__ Wql,
              const __half* __restrict__ Wkh, const __half* __restrict__ Wkl,
              const __half* __restrict__ Wvh, const __half* __restrict__ Wvl,
              __half* __restrict__ Cqh, __half* __restrict__ Cql,
              __half* __restrict__ Ckh, __half* __restrict__ Ckl,
              __half* __restrict__ Cvh, __half* __restrict__ Cvl) {
    extern __shared__ char dsm[];
    const int z = blockIdx.z;
    const __half* Wh = (z == 0) ? Wqh : (z == 1) ? Wkh : Wvh;
    const __half* Wl = (z == 0) ? Wql : (z == 1) ? Wkl : Wvl;
    __half* Ch = (z == 0) ? Cqh : (z == 1) ? Ckh : Cvh;
    __half* Cl = (z == 0) ? Cql : (z == 1) ? Ckl : Cvl;
    gemm_body<0, 1, 3>(Ah, Al, Wh, Wl, nullptr, nullptr, Ch, Cl,
                       D_, D_, blockIdx.y * 128, blockIdx.x * 128, dsm);
}

// ---------------- flash attention with mma.sync (3-term fp16 splits) ----------------
#define ATT_STAGE 33792
#define ATT_SMEM  (32768 + 2 * ATT_STAGE)

__global__ __launch_bounds__(256, 1)
void attn_mma_kernel(const __half* __restrict__ qh, const __half* __restrict__ ql,
                     const __half* __restrict__ kh, const __half* __restrict__ kl,
                     const __half* __restrict__ vh, const __half* __restrict__ vl,
                     const int* __restrict__ coords,
                     __half* __restrict__ aoh, __half* __restrict__ aol) {
    extern __shared__ char dsm[];
    const uint32_t sb = s2u(dsm);

    const int tid  = threadIdx.x;
    const int wid  = tid >> 5;
    const int lane = tid & 31;
    const int qt = blockIdx.x & 7;
    const int h  = (blockIdx.x >> 3) & 15;
    const int b  = blockIdx.x >> 7;
    const int qbase = qt * 128;

    const float slope = exp2f(-0.5f * (float)(h + 1));
    const float scale = 0.125f;

    const int r0 = wid * 16 + (lane >> 2);
    const int grow0 = b * N_ + qbase + r0;
    const float xi0 = (float)coords[grow0 * 2 + 0];
    const float yi0 = (float)coords[grow0 * 2 + 1];
    const float xi1 = (float)coords[(grow0 + 8) * 2 + 0];
    const float yi1 = (float)coords[(grow0 + 8) * 2 + 1];

    {
        const int rr = tid >> 3, cc = tid & 7;
#pragma unroll
        for (int j = 0; j < 4; j++) {
            const int r = rr + 32 * j;
            const size_t go = (size_t)(b * N_ + qbase + r) * D_ + h * HD_ + cc * 8;
            const uint32_t off = SWZ((uint32_t)(r * 128 + cc * 16));
            cp_async16(sb + off, qh + go);
            cp_async16(sb + 16384 + off, ql + go);
        }
    }
    CP_COMMIT();

    auto load_kv = [&](int t, int buf) {
        const uint32_t st = sb + 32768 + buf * ATT_STAGE;
        const int kt = t * 64;
        const int rr = tid >> 2, cc = tid & 3;
        const size_t gbase = (size_t)(b * N_ + kt) * D_ + h * HD_;
        const __half* G[4] = { kh + gbase, kl + gbase, vh + gbase, vl + gbase };
#pragma unroll
        for (int m = 0; m < 4; m++) {
#pragma unroll
            for (int j = 0; j < 2; j++) {
                const int ch = cc + 4 * j;
                cp_async16(st + m * 8192 + SWZ((uint32_t)(rr * 128 + ch * 16)),
                           G[m] + (size_t)rr * D_ + ch * 8);
            }
        }
        if (tid < 32)
            cp_async16(st + 32768 + tid * 16,
                       (const char*)coords + (size_t)(b * N_ + kt) * 8 + tid * 16);
    };

    load_kv(0, 0);
    CP_COMMIT();

    float m0 = -1e30f, m1 = -1e30f, l0 = 0.f, l1 = 0.f;
    float acc_o[8][4];
#pragma unroll
    for (int f = 0; f < 8; f++)
#pragma unroll
        for (int t = 0; t < 4; t++) acc_o[f][t] = 0.f;

    const int aRow  = wid * 16 + (lane & 15);
    const int aCol  = (lane >> 4) * 8;
    const int bRowK = ((lane >> 4) << 3) + (lane & 7);
    const int bColK = ((lane >> 3) & 1) * 8;
    const int vRow  = ((lane >> 3) & 1) * 8 + (lane & 7);
    const int vCol  = (lane >> 4) * 8;

    for (int t = 0; t < 16; t++) {
        const int buf = t & 1;
        if (t + 1 < 16) { load_kv(t + 1, 1 - buf); CP_COMMIT(); CP_WAIT(1); }
        else            { CP_WAIT(0); }
        __syncthreads();

        const uint32_t st = sb + 32768 + buf * ATT_STAGE;
        const uint32_t sKh = st, sKl = st + 8192, sVh = st + 16384, sVl = st + 24576;
        const int2* kco = (const int2*)(dsm + 32768 + buf * ATT_STAGE + 32768);

        float accs[8][4];
#pragma unroll
        for (int f = 0; f < 8; f++)
#pragma unroll
            for (int u = 0; u < 4; u++) accs[f][u] = 0.f;

#pragma unroll
        for (int ks = 0; ks < 4; ks++) {
            const int kc = ks * 16;
            uint32_t ah[4], al[4];
            const uint32_t aoff = SWZ((uint32_t)(aRow * 128 + (kc + aCol) * 2));
            ldsm4(ah, sb + aoff);
            ldsm4(al, sb + 16384 + aoff);
#pragma unroll
            for (int nh = 0; nh < 4; nh++) {
                const uint32_t boff = SWZ((uint32_t)((nh * 16 + bRowK) * 128 + (kc + bColK) * 2));
                uint32_t tb[4], tl[4];
                ldsm4(tb, sKh + boff);
                ldsm4(tl, sKl + boff);
                uint32_t bh0[2] = { tb[0], tb[1] }, bh1[2] = { tb[2], tb[3] };
                uint32_t bl0[2] = { tl[0], tl[1] }, bl1[2] = { tl[2], tl[3] };
                mma16816(accs[nh*2],   ah, bh0);
                mma16816(accs[nh*2],   ah, bl0);
                mma16816(accs[nh*2],   al, bh0);
                mma16816(accs[nh*2+1], ah, bh1);
                mma16816(accs[nh*2+1], ah, bl1);
                mma16816(accs[nh*2+1], al, bh1);
            }
        }

#pragma unroll
        for (int f = 0; f < 8; f++) {
            const int c = f * 8 + (lane & 3) * 2;
            const int2 ca = kco[c], cb = kco[c + 1];
            const float xa = (float)ca.x, ya = (float)ca.y;
            const float xb = (float)cb.x, yb = (float)cb.y;
            accs[f][0] = fmaf(accs[f][0], scale, slope * (fabsf(xi0 - xa) + fabsf(yi0 - ya)));
            accs[f][1] = fmaf(accs[f][1], scale, slope * (fabsf(xi0 - xb) + fabsf(yi0 - yb)));
            accs[f][2] = fmaf(accs[f][2], scale, slope * (fabsf(xi1 - xa) + fabsf(yi1 - ya)));
            accs[f][3] = fmaf(accs[f][3], scale, slope * (fabsf(xi1 - xb) + fabsf(yi1 - yb)));
        }

        float mx0 = -1e30f, mx1 = -1e30f;
#pragma unroll
        for (int f = 0; f < 8; f++) {
            mx0 = fmaxf(mx0, fmaxf(accs[f][0], accs[f][1]));
            mx1 = fmaxf(mx1, fmaxf(accs[f][2], accs[f][3]));
        }
        mx0 = fmaxf(mx0, __shfl_xor_sync(0xffffffffu, mx0, 1));
        mx0 = fmaxf(mx0, __shfl_xor_sync(0xffffffffu, mx0, 2));
        mx1 = fmaxf(mx1, __shfl_xor_sync(0xffffffffu, mx1, 1));
        mx1 = fmaxf(mx1, __shfl_xor_sync(0xffffffffu, mx1, 2));
        const float nm0 = fmaxf(m0, mx0), nm1 = fmaxf(m1, mx1);
        const float cr0 = __expf(m0 - nm0), cr1 = __expf(m1 - nm1);
        m0 = nm0; m1 = nm1;
        l0 *= cr0; l1 *= cr1;
#pragma unroll
        for (int f = 0; f < 8; f++) {
            acc_o[f][0] *= cr0; acc_o[f][1] *= cr0;
            acc_o[f][2] *= cr1; acc_o[f][3] *= cr1;
        }
#pragma unroll
        for (int f = 0; f < 8; f++) {
            accs[f][0] = __expf(accs[f][0] - nm0);
            accs[f][1] = __expf(accs[f][1] - nm0);
            accs[f][2] = __expf(accs[f][2] - nm1);
            accs[f][3] = __expf(accs[f][3] - nm1);
            l0 += accs[f][0] + accs[f][1];
            l1 += accs[f][2] + accs[f][3];
        }

#pragma unroll
        for (int kg = 0; kg < 4; kg++) {
            const float* s0 = accs[2 * kg];
            const float* s1 = accs[2 * kg + 1];
            uint32_t pah[4], pal[4];
            pack_hl(s0[0], s0[1], pah[0], pal[0]);
            pack_hl(s0[2], s0[3], pah[1], pal[1]);
            pack_hl(s1[0], s1[1], pah[2], pal[2]);
            pack_hl(s1[2], s1[3], pah[3], pal[3]);
#pragma unroll
            for (int vi = 0; vi < 4; vi++) {
                const uint32_t voff =
                    SWZ((uint32_t)((kg * 16 + vRow) * 128 + (vi * 16 + vCol) * 2));
                uint32_t tv[4], tw[4];
                ldsm4t(tv, sVh + voff);
                ldsm4t(tw, sVl + voff);
                uint32_t bvh0[2] = { tv[0], tv[1] }, bvh1[2] = { tv[2], tv[3] };
                uint32_t bvl0[2] = { tw[0], tw[1] }, bvl1[2] = { tw[2], tw[3] };
                mma16816(acc_o[vi*2],   pah, bvh0);
                mma16816(acc_o[vi*2],   pah, bvl0);
                mma16816(acc_o[vi*2],   pal, bvh0);
                mma16816(acc_o[vi*2+1], pah, bvh1);
                mma16816(acc_o[vi*2+1], pah, bvl1);
                mma16816(acc_o[vi*2+1], pal, bvh1);
            }
        }
        __syncthreads();
    }

    l0 += __shfl_xor_sync(0xffffffffu, l0, 1);
    l0 += __shfl_xor_sync(0xffffffffu, l0, 2);
    l1 += __shfl_xor_sync(0xffffffffu, l1, 1);
    l1 += __shfl_xor_sync(0xffffffffu, l1, 2);
    const float inv0 = 1.f / l0, inv1 = 1.f / l1;
#pragma unroll
    for (int f = 0; f < 8; f++) {
        const int c = f * 8 + (lane & 3) * 2;
        const size_t base0 = (size_t)grow0 * D_ + h * HD_ + c;
        const size_t base1 = (size_t)(grow0 + 8) * D_ + h * HD_ + c;
        uint32_t hp, lp;
        pack_hl(acc_o[f][0] * inv0, acc_o[f][1] * inv0, hp, lp);
        *(uint32_t*)(aoh + base0) = hp;
        *(uint32_t*)(aol + base0) = lp;
        pack_hl(acc_o[f][2] * inv1, acc_o[f][3] * inv1, hp, lp);
        *(uint32_t*)(aoh + base1) = hp;
        *(uint32_t*)(aol + base1) = lp;
    }
}

// ---------------- fused residual add + LayerNorm (+ optional plain fp16 emit) -------
__global__ __launch_bounds__(256)
void add_ln_kernel(const float* __restrict__ a, const float* __restrict__ bsum,
                   const float* __restrict__ g, const float* __restrict__ be,
                   float* __restrict__ out, __half* __restrict__ hi) {
    const int row = blockIdx.x;
    const int tid = threadIdx.x;
    const float* pa = a    + (size_t)row * D_;
    const float* pb = bsum + (size_t)row * D_;

    float v[4];
    float s = 0.f, ss = 0.f;
#pragma unroll
    for (int i = 0; i < 4; i++) {
        const int c = tid + 256 * i;
        const float t = pa[c] + pb[c];
        v[i] = t; s += t; ss = fmaf(t, t, ss);
    }
#pragma unroll
    for (int o = 16; o > 0; o >>= 1) {
        s  += __shfl_xor_sync(0xffffffffu, s,  o);
        ss += __shfl_xor_sync(0xffffffffu, ss, o);
    }
    __shared__ float rs[8], rss[8];
    __shared__ float smu, sinv;
    const int w = tid >> 5;
    if ((tid & 31) == 0) { rs[w] = s; rss[w] = ss; }
    __syncthreads();
    if (tid == 0) {
        float S = 0.f, SS = 0.f;
#pragma unroll
        for (int i = 0; i < 8; i++) { S += rs[i]; SS += rss[i]; }
        const float mu  = S * (1.f / 1024.f);
        const float var = SS * (1.f / 1024.f) - mu * mu;
        smu = mu; sinv = rsqrtf(var + 1e-5f);
    }
    __syncthreads();
    const float mu = smu, inv = sinv;
#pragma unroll
    for (int i = 0; i < 4; i++) {
        const int c = tid + 256 * i;
        const float o = (v[i] - mu) * inv * g[c] + be[c];
        out[(size_t)row * D_ + c] = o;
        if (hi) hi[(size_t)row * D_ + c] = __float2half_rn(o);
    }
}

// ---------------- launch ----------------
extern "C" void kernel_launch(void* const* d_in, const int* in_sizes, int n_in,
                              void* d_out, int out_size) {
    const float* src    = (const float*)d_in[0];
    const int*   coords = (const int*)  d_in[1];
    const float* Wq = (const float*)d_in[2];
    const float* Wk = (const float*)d_in[3];
    const float* Wv = (const float*)d_in[4];
    const float* Wo = (const float*)d_in[5];
    const float* W1 = (const float*)d_in[6];
    const float* b1 = (const float*)d_in[7];
    const float* W2 = (const float*)d_in[8];
    const float* b2 = (const float*)d_in[9];
    const float* g1 = (const float*)d_in[10];
    const float* be1= (const float*)d_in[11];
    const float* g2 = (const float*)d_in[12];
    const float* be2= (const float*)d_in[13];
    float* out = (float*)d_out;

    void *pt, *px;
    cudaGetSymbolAddress(&pt, g_t);
    cudaGetSymbolAddress(&px, g_x);

    void *srch,*srcl,*wqh,*wql,*wkh,*wkl,*wvh,*wvl,*woh,*wol,*w1h,*w1l,*w2h,*w2l;
    void *xh,*aoh,*aol,*ffh,*qhh,*qll,*khh,*kll,*vhh,*vll;
    cudaGetSymbolAddress(&srch, s_src_h); cudaGetSymbolAddress(&srcl, s_src_l);
    cudaGetSymbolAddress(&wqh, s_wq_h);   cudaGetSymbolAddress(&wql, s_wq_l);
    cudaGetSymbolAddress(&wkh, s_wk_h);   cudaGetSymbolAddress(&wkl, s_wk_l);
    cudaGetSymbolAddress(&wvh, s_wv_h);   cudaGetSymbolAddress(&wvl, s_wv_l);
    cudaGetSymbolAddress(&woh, s_wo_h);   cudaGetSymbolAddress(&wol, s_wo_l);
    cudaGetSymbolAddress(&w1h, s_w1_h);   cudaGetSymbolAddress(&w1l, s_w1_l);
    cudaGetSymbolAddress(&w2h, s_w2_h);   cudaGetSymbolAddress(&w2l, s_w2_l);
    cudaGetSymbolAddress(&xh,  s_x_h);
    cudaGetSymbolAddress(&aoh, s_ao_h);   cudaGetSymbolAddress(&aol, s_ao_l);
    cudaGetSymbolAddress(&ffh, s_ff_h);
    cudaGetSymbolAddress(&qhh, s_q_h);    cudaGetSymbolAddress(&qll, s_q_l);
    cudaGetSymbolAddress(&khh, s_k_h);    cudaGetSymbolAddress(&kll, s_k_l);
    cudaGetSymbolAddress(&vhh, s_v_h);    cudaGetSymbolAddress(&vll, s_v_l);

    cudaFuncSetAttribute((const void*)mma_gemm<0, 0, 3>,
                         cudaFuncAttributeMaxDynamicSharedMemorySize, GEMM_SMEM_BYTES);
    cudaFuncSetAttribute((const void*)mma_gemm<1, 2, 2>,
                         cudaFuncAttributeMaxDynamicSharedMemorySize, GEMM_SMEM_BYTES);
    cudaFuncSetAttribute((const void*)mma_gemm<0, 0, 2>,
                         cudaFuncAttributeMaxDynamicSharedMemorySize, GEMM_SMEM_BYTES);
    cudaFuncSetAttribute((const void*)qkv_gemm,
                         cudaFuncAttributeMaxDynamicSharedMemorySize, GEMM_SMEM_BYTES);
    cudaFuncSetAttribute((const void*)attn_mma_kernel,
                         cudaFuncAttributeMaxDynamicSharedMemorySize, ATT_SMEM);

    const int nSrc4 = M_ * D_ / 4;
    const int nW4   = D_ * D_ / 4;
    const int nW14  = FF_ * D_ / 4;

    const dim3 blk(256);
    const dim3 gD(D_ / 128, M_ / 128);        // (8, 32)
    const dim3 gQKV(D_ / 128, M_ / 128, 3);   // (8, 32, 3)
    const dim3 gF(FF_ / 128, M_ / 128);       // (32, 32)

    // splits
    split_kernel<<<nSrc4 / 256, 256>>>((const float4*)src, (uint2*)srch, (uint2*)srcl, nSrc4);
    split_kernel<<<nW4 / 256, 256>>>((const float4*)Wq, (uint2*)wqh, (uint2*)wql, nW4);
    split_kernel<<<nW4 / 256, 256>>>((const float4*)Wk, (uint2*)wkh, (uint2*)wkl, nW4);
    split_kernel<<<nW4 / 256, 256>>>((const float4*)Wv, (uint2*)wvh, (uint2*)wvl, nW4);

    // fused QKV projections (3-term, fp16 hi/lo out)
    qkv_gemm<<<gQKV, blk, GEMM_SMEM_BYTES>>>(
        (const __half*)srch, (const __half*)srcl,
        (const __half*)wqh,  (const __half*)wql,
        (const __half*)wkh,  (const __half*)wkl,
        (const __half*)wvh,  (const __half*)wvl,
        (__half*)qhh, (__half*)qll,
        (__half*)khh, (__half*)kll,
        (__half*)vhh, (__half*)vll);

    // remaining weight splits
    split_kernel<<<nW4 / 256, 256>>>((const float4*)Wo, (uint2*)woh, (uint2*)wol, nW4);
    split_kernel<<<nW14 / 256, 256>>>((const float4*)W1, (uint2*)w1h, (uint2*)w1l, nW14);
    split_kernel<<<nW14 / 256, 256>>>((const float4*)W2, (uint2*)w2h, (uint2*)w2l, nW14);

    // flash attention (3-term fp16)
    attn_mma_kernel<<<512, 256, ATT_SMEM>>>(
        (const __half*)qhh, (const __half*)qll,
        (const __half*)khh, (const __half*)kll,
        (const __half*)vhh, (const __half*)vll,
        coords, (__half*)aoh, (__half*)aol);

    // output projection (3-term) -> fp32 t ; residual + LN1 -> x (fp32 + plain fp16)
    mma_gemm<0, 0, 3><<<gD, blk, GEMM_SMEM_BYTES>>>(
        (const __half*)aoh, (const __half*)aol,
        (const __half*)woh, (const __half*)wol,
        nullptr, (float*)pt, nullptr, nullptr, D_, D_);
    add_ln_kernel<<<M_, 256>>>(src, (const float*)pt, g1, be1, (float*)px, (__half*)xh);

    // FFN1 (2-term: x plain fp16, W1 split; bias + exact gelu; plain fp16 out)
    mma_gemm<1, 2, 2><<<gF, blk, GEMM_SMEM_BYTES>>>(
        (const __half*)xh,  nullptr,
        (const __half*)w1h, (const __half*)w1l,
        b1, nullptr, (__half*)ffh, nullptr, FF_, D_);

    // FFN2 (2-term: ff plain fp16, W2 split; bias; fp32 out) ; residual + LN2 -> out
    mma_gemm<0, 0, 2><<<gD, blk, GEMM_SMEM_BYTES>>>(
        (const __half*)ffh, nullptr,
        (const __half*)w2h, (const __half*)w2l,
        b2, (float*)pt, nullptr, nullptr, D_, FF_);
    add_ln_kernel<<<M_, 256>>>((const float*)px, (const float*)pt, g2, be2, out, nullptr);
}

// round 10
// speedup vs baseline: 1.3914x; 1.1387x over previous
#include <cuda_runtime.h>
#include <cuda_fp16.h>
#include <math.h>
#include <stdint.h>

#define B_   4
#define N_   1024
#define D_   1024
#define H_   16
#define HD_  64
#define FF_  4096
#define M_   (B_ * N_)   // 4096 rows

// ---------------- scratch (static device globals; no allocs allowed) ----------------
__device__ float g_t [M_ * D_];   // src2 / ffn2 output temp (fp32)
__device__ float g_x [M_ * D_];   // post-LN1 activations (fp32)

// fp16 buffers (hi/lo splits for weights + K; plain fp16 activations)
__device__ __half s_src_h[M_ * D_];
__device__ __half s_wq_h [D_ * D_],  s_wq_l [D_ * D_];
__device__ __half s_wk_h [D_ * D_],  s_wk_l [D_ * D_];
__device__ __half s_wv_h [D_ * D_],  s_wv_l [D_ * D_];
__device__ __half s_wo_h [D_ * D_],  s_wo_l [D_ * D_];
__device__ __half s_w1_h [FF_ * D_], s_w1_l [FF_ * D_];
__device__ __half s_w2_h [D_ * FF_], s_w2_l [D_ * FF_];
__device__ __half s_x_h  [M_ * D_];
__device__ __half s_ao_h [M_ * D_];
__device__ __half s_ff_h [M_ * FF_];
__device__ __half s_q_h  [M_ * D_];
__device__ __half s_k_h  [M_ * D_],  s_k_l  [M_ * D_];
__device__ __half s_v_h  [M_ * D_];

// ---------------- PTX helpers (Ampere-era only: valid at compute_103 base) ----------
__device__ __forceinline__ uint32_t s2u(const void* p) {
    uint32_t a;
    asm("{ .reg .u64 t; cvta.to.shared.u64 t, %1; cvt.u32.u64 %0, t; }" : "=r"(a) : "l"(p));
    return a;
}
__device__ __forceinline__ void cp_async16(uint32_t saddr, const void* g) {
    asm volatile("cp.async.cg.shared.global [%0], [%1], 16;" :: "r"(saddr), "l"(g) : "memory");
}
#define CP_COMMIT()  asm volatile("cp.async.commit_group;" ::: "memory")
#define CP_WAIT(n)   asm volatile("cp.async.wait_group %0;" :: "n"(n) : "memory")

__device__ __forceinline__ void ldsm4(uint32_t* r, uint32_t addr) {
    asm volatile("ldmatrix.sync.aligned.m8n8.x4.shared.b16 {%0,%1,%2,%3}, [%4];"
                 : "=r"(r[0]), "=r"(r[1]), "=r"(r[2]), "=r"(r[3]) : "r"(addr));
}
__device__ __forceinline__ void ldsm4t(uint32_t* r, uint32_t addr) {
    asm volatile("ldmatrix.sync.aligned.m8n8.x4.trans.shared.b16 {%0,%1,%2,%3}, [%4];"
                 : "=r"(r[0]), "=r"(r[1]), "=r"(r[2]), "=r"(r[3]) : "r"(addr));
}
__device__ __forceinline__ void mma16816(float* c, const uint32_t* a, const uint32_t* b) {
    asm volatile(
        "mma.sync.aligned.m16n8k16.row.col.f32.f16.f16.f32 "
        "{%0,%1,%2,%3}, {%4,%5,%6,%7}, {%8,%9}, {%0,%1,%2,%3};"
        : "+f"(c[0]), "+f"(c[1]), "+f"(c[2]), "+f"(c[3])
        : "r"(a[0]), "r"(a[1]), "r"(a[2]), "r"(a[3]), "r"(b[0]), "r"(b[1]));
}

#define SWZ(o) ((o) ^ (((o) >> 3) & 0x70))

__device__ __forceinline__ void pack_hl(float a, float b, uint32_t& hi, uint32_t& lo) {
    __half ha = __float2half_rn(a), hb = __float2half_rn(b);
    __half2 hp = __halves2half2(ha, hb);
    hi = *(uint32_t*)&hp;
    __half2 lp = __halves2half2(
        __float2half_rn(a - __half2float(ha)),
        __float2half_rn(b - __half2float(hb)));
    lo = *(uint32_t*)&lp;
}
__device__ __forceinline__ uint32_t pack_h(float a, float b) {
    __half2 hp = __halves2half2(__float2half_rn(a), __float2half_rn(b));
    return *(uint32_t*)&hp;
}

// ---------------- split fp32 -> fp16 (hi, + lo if given) ----------------
__global__ __launch_bounds__(256)
void split_kernel(const float4* __restrict__ x, uint2* __restrict__ hi,
                  uint2* __restrict__ lo, int n4) {
    int i = blockIdx.x * 256 + threadIdx.x;
    if (i >= n4) return;
    float4 v = x[i];
    uint32_t h0, l0, h1, l1;
    pack_hl(v.x, v.y, h0, l0);
    pack_hl(v.z, v.w, h1, l1);
    hi[i] = make_uint2(h0, h1);
    if (lo) lo[i] = make_uint2(l0, l1);
}

// ---------------- HMMA GEMM body: 128x128 tile, 256 thr, warptile 64x32 ------------
// BK=64, 2-stage cp.async. stage: Ah[0,16K) Al[16K,32K) Wh[32K,48K) Wl[48K,64K)
// TERMS==3: AhWh + AhWl + AlWh ; TERMS==2: AhWh + AhWl (A plain fp16)
// OUTMODE: 0 = fp32, 1 = fp16 hi (+ lo if Cl != nullptr)
#define STAGE_BYTES 65536
#define GEMM_SMEM_BYTES (2 * STAGE_BYTES)

template <int ACT, int OUTMODE, int TERMS>
__device__ __forceinline__
void gemm_body(const __half* __restrict__ Ah, const __half* __restrict__ Al,
               const __half* __restrict__ Wh, const __half* __restrict__ Wl,
               const float* __restrict__ bias,
               float* __restrict__ Cf,
               __half* __restrict__ Ch, __half* __restrict__ Cl,
               int Nn, int K, int mBase, int nBase, char* dsm) {
    const uint32_t sb = s2u(dsm);

    const int tid  = threadIdx.x;
    const int wid  = tid >> 5;
    const int lane = tid & 31;
    const int wm   = wid & 1;        // 2 warps in m (64 rows each)
    const int wn   = wid >> 1;       // 4 warps in n (32 cols each)
    const int NC = K / 64;

    const int r0 = tid >> 3;
    const int c0 = tid & 7;

    const __half* pAh = Ah + (size_t)(mBase + r0) * K + c0 * 8;
    const __half* pAl = (TERMS == 3) ? Al + (size_t)(mBase + r0) * K + c0 * 8 : nullptr;
    const __half* pWh = Wh + (size_t)(nBase + r0) * K + c0 * 8;
    const __half* pWl = Wl + (size_t)(nBase + r0) * K + c0 * 8;

    auto load_stage = [&](int buf, int kcol) {
        const uint32_t stage = sb + buf * STAGE_BYTES;
#pragma unroll
        for (int j = 0; j < 4; j++) {
            const int r = r0 + 32 * j;
            const uint32_t off = SWZ((uint32_t)(r * 128 + c0 * 16));
            cp_async16(stage + off,         pAh + (size_t)(32 * j) * K + kcol);
            if (TERMS == 3)
                cp_async16(stage + 16384 + off, pAl + (size_t)(32 * j) * K + kcol);
            cp_async16(stage + 32768 + off, pWh + (size_t)(32 * j) * K + kcol);
            cp_async16(stage + 49152 + off, pWl + (size_t)(32 * j) * K + kcol);
        }
    };

    float acc[4][4][4];
#pragma unroll
    for (int i = 0; i < 4; i++)
#pragma unroll
        for (int j = 0; j < 4; j++)
#pragma unroll
            for (int t = 0; t < 4; t++) acc[i][j][t] = 0.f;

    const int aRow = wm * 64 + (lane & 15);
    const int aColSel = (lane >> 4) * 8;
    const int bRow = wn * 32 + ((lane >> 4) << 3) + (lane & 7);
    const int bColSel = ((lane >> 3) & 1) * 8;

    load_stage(0, 0);
    CP_COMMIT();

    for (int c = 0; c < NC; c++) {
        if (c + 1 < NC) {
            load_stage((c + 1) & 1, (c + 1) * 64);
            CP_COMMIT();
            CP_WAIT(1);
        } else {
            CP_WAIT(0);
        }
        __syncthreads();

        const uint32_t stage = sb + (c & 1) * STAGE_BYTES;
        const uint32_t sAh = stage, sAl = stage + 16384;
        const uint32_t sWh = stage + 32768, sWl = stage + 49152;

#pragma unroll
        for (int ks = 0; ks < 4; ks++) {
            const int kc = ks * 16;
            uint32_t ah[4][4], al[4][4];
#pragma unroll
            for (int fm = 0; fm < 4; fm++) {
                const uint32_t off = SWZ((uint32_t)((aRow + fm * 16) * 128 + (kc + aColSel) * 2));
                ldsm4(ah[fm], sAh + off);
                if (TERMS == 3) ldsm4(al[fm], sAl + off);
            }
            uint32_t bh[4][2], bl[4][2];
#pragma unroll
            for (int ng = 0; ng < 2; ng++) {
                const uint32_t off = SWZ((uint32_t)((bRow + ng * 16) * 128 + (kc + bColSel) * 2));
                uint32_t t[4];
                ldsm4(t, sWh + off);
                bh[ng*2][0] = t[0]; bh[ng*2][1] = t[1];
                bh[ng*2+1][0] = t[2]; bh[ng*2+1][1] = t[3];
                ldsm4(t, sWl + off);
                bl[ng*2][0] = t[0]; bl[ng*2][1] = t[1];
                bl[ng*2+1][0] = t[2]; bl[ng*2+1][1] = t[3];
            }
#pragma unroll
            for (int fm = 0; fm < 4; fm++)
#pragma unroll
                for (int fn = 0; fn < 4; fn++) {
                    mma16816(acc[fm][fn], ah[fm], bh[fn]);
                    mma16816(acc[fm][fn], ah[fm], bl[fn]);
                    if (TERMS == 3) mma16816(acc[fm][fn], al[fm], bh[fn]);
                }
        }
        __syncthreads();
    }

    // ---- epilogue ----
    const int erow = mBase + wm * 64 + (lane >> 2);
    const int ecol = nBase + wn * 32 + (lane & 3) * 2;
#pragma unroll
    for (int fm = 0; fm < 4; fm++) {
#pragma unroll
        for (int fn = 0; fn < 4; fn++) {
            const int col = ecol + fn * 8;
#pragma unroll
            for (int half = 0; half < 2; half++) {
                const int row = erow + fm * 16 + half * 8;
                float v0 = acc[fm][fn][half * 2 + 0];
                float v1 = acc[fm][fn][half * 2 + 1];
                if (bias) { v0 += bias[col]; v1 += bias[col + 1]; }
                if (ACT == 1) {
                    v0 = 0.5f * v0 * (1.f + erff(v0 * 0.70710678118654752f));
                    v1 = 0.5f * v1 * (1.f + erff(v1 * 0.70710678118654752f));
                }
                const size_t base = (size_t)row * Nn + col;
                if (OUTMODE == 1) {
                    uint32_t hp, lp;
                    pack_hl(v0, v1, hp, lp);
                    *(uint32_t*)(Ch + base) = hp;
                    if (Cl) *(uint32_t*)(Cl + base) = lp;
                } else {
                    *(float2*)(Cf + base) = make_float2(v0, v1);
                }
            }
        }
    }
}

template <int ACT, int OUTMODE, int TERMS>
__global__ __launch_bounds__(256, 1)
void mma_gemm(const __half* __restrict__ Ah, const __half* __restrict__ Al,
              const __half* __restrict__ Wh, const __half* __restrict__ Wl,
              const float* __restrict__ bias,
              float* __restrict__ Cf,
              __half* __restrict__ Ch, __half* __restrict__ Cl,
              int Nn, int K) {
    extern __shared__ char dsm[];
    gemm_body<ACT, OUTMODE, TERMS>(Ah, Al, Wh, Wl, bias, Cf, Ch, Cl,
                                   Nn, K, blockIdx.y * 128, blockIdx.x * 128, dsm);
}

// fused QKV (2-term: src plain fp16, W split). K emits hi+lo; Q,V hi only.
__global__ __launch_bounds__(256, 1)
void qkv_gemm(const __half* __restrict__ Ah,
              const __half* __restrict__ Wqh, const __half* __restrict__ Wql,
              const __half* __restrict__ Wkh, const __half* __restrict__ Wkl,
              const __half* __restrict__ Wvh, const __half* __restrict__ Wvl,
              __half* __restrict__ Cqh,
              __half* __restrict__ Ckh, __half* __restrict__ Ckl,
              __half* __restrict__ Cvh) {
    extern __shared__ char dsm[];
    const int z = blockIdx.z;
    const __half* Wh = (z == 0) ? Wqh : (z == 1) ? Wkh : Wvh;
    const __half* Wl = (z == 0) ? Wql : (z == 1) ? Wkl : Wvl;
    __half* Ch = (z == 0) ? Cqh : (z == 1) ? Ckh : Cvh;
    __half* Cl = (z == 1) ? Ckl : nullptr;
    gemm_body<0, 1, 2>(Ah, nullptr, Wh, Wl, nullptr, nullptr, Ch, Cl,
                       D_, D_, blockIdx.y * 128, blockIdx.x * 128, dsm);
}

// ---------------- flash attention, 2-term fp16: S=Q(Kh+Kl), O=(Ph+Pl)Vh -------------
// smem: Q[0,16K), stages at 16384 + s*25088: Kh +0, Kl +8192, Vh +16384, coords +24576
#define ATT_STAGE 25088
#define ATT_SMEM  (16384 + 2 * ATT_STAGE)

__global__ __launch_bounds__(256, 1)
void attn_mma_kernel(const __half* __restrict__ qh,
                     const __half* __restrict__ kh, const __half* __restrict__ kl,
                     const __half* __restrict__ vh,
                     const int* __restrict__ coords,
                     __half* __restrict__ aoh) {
    extern __shared__ char dsm[];
    const uint32_t sb = s2u(dsm);

    const int tid  = threadIdx.x;
    const int wid  = tid >> 5;
    const int lane = tid & 31;
    const int qt = blockIdx.x & 7;
    const int h  = (blockIdx.x >> 3) & 15;
    const int b  = blockIdx.x >> 7;
    const int qbase = qt * 128;

    const float slope = exp2f(-0.5f * (float)(h + 1));
    const float scale = 0.125f;

    const int r0 = wid * 16 + (lane >> 2);
    const int grow0 = b * N_ + qbase + r0;
    const float xi0 = (float)coords[grow0 * 2 + 0];
    const float yi0 = (float)coords[grow0 * 2 + 1];
    const float xi1 = (float)coords[(grow0 + 8) * 2 + 0];
    const float yi1 = (float)coords[(grow0 + 8) * 2 + 1];

    {   // Q (plain fp16, 16 KB)
        const int rr = tid >> 1, cc = tid & 1;
#pragma unroll
        for (int j = 0; j < 1; j++) { }
        // 128 rows x 128B rows: 256 threads x 4 chunks
        const int rr2 = tid >> 3, cc2 = tid & 7;
#pragma unroll
        for (int j = 0; j < 4; j++) {
            const int r = rr2 + 32 * j;
            const size_t go = (size_t)(b * N_ + qbase + r) * D_ + h * HD_ + cc2 * 8;
            cp_async16(sb + SWZ((uint32_t)(r * 128 + cc2 * 16)), qh + go);
        }
        (void)rr; (void)cc;
    }
    CP_COMMIT();

    auto load_kv = [&](int t, int buf) {
        const uint32_t st = sb + 16384 + buf * ATT_STAGE;
        const int kt = t * 64;
        const int rr = tid >> 2, cc = tid & 3;
        const size_t gbase = (size_t)(b * N_ + kt) * D_ + h * HD_;
        const __half* G[3] = { kh + gbase, kl + gbase, vh + gbase };
#pragma unroll
        for (int m = 0; m < 3; m++) {
#pragma unroll
            for (int j = 0; j < 2; j++) {
                const int ch = cc + 4 * j;
                cp_async16(st + m * 8192 + SWZ((uint32_t)(rr * 128 + ch * 16)),
                           G[m] + (size_t)rr * D_ + ch * 8);
            }
        }
        if (tid < 32)
            cp_async16(st + 24576 + tid * 16,
                       (const char*)coords + (size_t)(b * N_ + kt) * 8 + tid * 16);
    };

    load_kv(0, 0);
    CP_COMMIT();

    float m0 = -1e30f, m1 = -1e30f, l0 = 0.f, l1 = 0.f;
    float acc_o[8][4];
#pragma unroll
    for (int f = 0; f < 8; f++)
#pragma unroll
        for (int t = 0; t < 4; t++) acc_o[f][t] = 0.f;

    const int aRow  = wid * 16 + (lane & 15);
    const int aCol  = (lane >> 4) * 8;
    const int bRowK = ((lane >> 4) << 3) + (lane & 7);
    const int bColK = ((lane >> 3) & 1) * 8;
    const int vRow  = ((lane >> 3) & 1) * 8 + (lane & 7);
    const int vCol  = (lane >> 4) * 8;

    for (int t = 0; t < 16; t++) {
        const int buf = t & 1;
        if (t + 1 < 16) { load_kv(t + 1, 1 - buf); CP_COMMIT(); CP_WAIT(1); }
        else            { CP_WAIT(0); }
        __syncthreads();

        const uint32_t st = sb + 16384 + buf * ATT_STAGE;
        const uint32_t sKh = st, sKl = st + 8192, sVh = st + 16384;
        const int2* kco = (const int2*)(dsm + 16384 + buf * ATT_STAGE + 24576);

        float accs[8][4];
#pragma unroll
        for (int f = 0; f < 8; f++)
#pragma unroll
            for (int u = 0; u < 4; u++) accs[f][u] = 0.f;

#pragma unroll
        for (int ks = 0; ks < 4; ks++) {
            const int kc = ks * 16;
            uint32_t ah[4];
            const uint32_t aoff = SWZ((uint32_t)(aRow * 128 + (kc + aCol) * 2));
            ldsm4(ah, sb + aoff);
#pragma unroll
            for (int nh = 0; nh < 4; nh++) {
                const uint32_t boff = SWZ((uint32_t)((nh * 16 + bRowK) * 128 + (kc + bColK) * 2));
                uint32_t tb[4], tl[4];
                ldsm4(tb, sKh + boff);
                ldsm4(tl, sKl + boff);
                uint32_t bh0[2] = { tb[0], tb[1] }, bh1[2] = { tb[2], tb[3] };
                uint32_t bl0[2] = { tl[0], tl[1] }, bl1[2] = { tl[2], tl[3] };
                mma16816(accs[nh*2],   ah, bh0);
                mma16816(accs[nh*2],   ah, bl0);
                mma16816(accs[nh*2+1], ah, bh1);
                mma16816(accs[nh*2+1], ah, bl1);
            }
        }

#pragma unroll
        for (int f = 0; f < 8; f++) {
            const int c = f * 8 + (lane & 3) * 2;
            const int2 ca = kco[c], cb = kco[c + 1];
            const float xa = (float)ca.x, ya = (float)ca.y;
            const float xb = (float)cb.x, yb = (float)cb.y;
            accs[f][0] = fmaf(accs[f][0], scale, slope * (fabsf(xi0 - xa) + fabsf(yi0 - ya)));
            accs[f][1] = fmaf(accs[f][1], scale, slope * (fabsf(xi0 - xb) + fabsf(yi0 - yb)));
            accs[f][2] = fmaf(accs[f][2], scale, slope * (fabsf(xi1 - xa) + fabsf(yi1 - ya)));
            accs[f][3] = fmaf(accs[f][3], scale, slope * (fabsf(xi1 - xb) + fabsf(yi1 - yb)));
        }

        float mx0 = -1e30f, mx1 = -1e30f;
#pragma unroll
        for (int f = 0; f < 8; f++) {
            mx0 = fmaxf(mx0, fmaxf(accs[f][0], accs[f][1]));
            mx1 = fmaxf(mx1, fmaxf(accs[f][2], accs[f][3]));
        }
        mx0 = fmaxf(mx0, __shfl_xor_sync(0xffffffffu, mx0, 1));
        mx0 = fmaxf(mx0, __shfl_xor_sync(0xffffffffu, mx0, 2));
        mx1 = fmaxf(mx1, __shfl_xor_sync(0xffffffffu, mx1, 1));
        mx1 = fmaxf(mx1, __shfl_xor_sync(0xffffffffu, mx1, 2));
        const float nm0 = fmaxf(m0, mx0), nm1 = fmaxf(m1, mx1);
        const float cr0 = __expf(m0 - nm0), cr1 = __expf(m1 - nm1);
        m0 = nm0; m1 = nm1;
        l0 *= cr0; l1 *= cr1;
#pragma unroll
        for (int f = 0; f < 8; f++) {
            acc_o[f][0] *= cr0; acc_o[f][1] *= cr0;
            acc_o[f][2] *= cr1; acc_o[f][3] *= cr1;
        }
#pragma unroll
        for (int f = 0; f < 8; f++) {
            accs[f][0] = __expf(accs[f][0] - nm0);
            accs[f][1] = __expf(accs[f][1] - nm0);
            accs[f][2] = __expf(accs[f][2] - nm1);
            accs[f][3] = __expf(accs[f][3] - nm1);
            l0 += accs[f][0] + accs[f][1];
            l1 += accs[f][2] + accs[f][3];
        }

        // ---- O += (Ph + Pl) Vh ----
#pragma unroll
        for (int kg = 0; kg < 4; kg++) {
            const float* s0 = accs[2 * kg];
            const float* s1 = accs[2 * kg + 1];
            uint32_t pah[4], pal[4];
            pack_hl(s0[0], s0[1], pah[0], pal[0]);
            pack_hl(s0[2], s0[3], pah[1], pal[1]);
            pack_hl(s1[0], s1[1], pah[2], pal[2]);
            pack_hl(s1[2], s1[3], pah[3], pal[3]);
#pragma unroll
            for (int vi = 0; vi < 4; vi++) {
                const uint32_t voff =
                    SWZ((uint32_t)((kg * 16 + vRow) * 128 + (vi * 16 + vCol) * 2));
                uint32_t tv[4];
                ldsm4t(tv, sVh + voff);
                uint32_t bvh0[2] = { tv[0], tv[1] }, bvh1[2] = { tv[2], tv[3] };
                mma16816(acc_o[vi*2],   pah, bvh0);
                mma16816(acc_o[vi*2],   pal, bvh0);
                mma16816(acc_o[vi*2+1], pah, bvh1);
                mma16816(acc_o[vi*2+1], pal, bvh1);
            }
        }
        __syncthreads();
    }

    l0 += __shfl_xor_sync(0xffffffffu, l0, 1);
    l0 += __shfl_xor_sync(0xffffffffu, l0, 2);
    l1 += __shfl_xor_sync(0xffffffffu, l1, 1);
    l1 += __shfl_xor_sync(0xffffffffu, l1, 2);
    const float inv0 = 1.f / l0, inv1 = 1.f / l1;
#pragma unroll
    for (int f = 0; f < 8; f++) {
        const int c = f * 8 + (lane & 3) * 2;
        const size_t base0 = (size_t)grow0 * D_ + h * HD_ + c;
        const size_t base1 = (size_t)(grow0 + 8) * D_ + h * HD_ + c;
        *(uint32_t*)(aoh + base0) = pack_h(acc_o[f][0] * inv0, acc_o[f][1] * inv0);
        *(uint32_t*)(aoh + base1) = pack_h(acc_o[f][2] * inv1, acc_o[f][3] * inv1);
    }
}

// ---------------- fused residual add + LayerNorm (+ optional plain fp16 emit) -------
__global__ __launch_bounds__(256)
void add_ln_kernel(const float* __restrict__ a, const float* __restrict__ bsum,
                   const float* __restrict__ g, const float* __restrict__ be,
                   float* __restrict__ out, __half* __restrict__ hi) {
    const int row = blockIdx.x;
    const int tid = threadIdx.x;
    const float* pa = a    + (size_t)row * D_;
    const float* pb = bsum + (size_t)row * D_;

    float v[4];
    float s = 0.f, ss = 0.f;
#pragma unroll
    for (int i = 0; i < 4; i++) {
        const int c = tid + 256 * i;
        const float t = pa[c] + pb[c];
        v[i] = t; s += t; ss = fmaf(t, t, ss);
    }
#pragma unroll
    for (int o = 16; o > 0; o >>= 1) {
        s  += __shfl_xor_sync(0xffffffffu, s,  o);
        ss += __shfl_xor_sync(0xffffffffu, ss, o);
    }
    __shared__ float rs[8], rss[8];
    __shared__ float smu, sinv;
    const int w = tid >> 5;
    if ((tid & 31) == 0) { rs[w] = s; rss[w] = ss; }
    __syncthreads();
    if (tid == 0) {
        float S = 0.f, SS = 0.f;
#pragma unroll
        for (int i = 0; i < 8; i++) { S += rs[i]; SS += rss[i]; }
        const float mu  = S * (1.f / 1024.f);
        const float var = SS * (1.f / 1024.f) - mu * mu;
        smu = mu; sinv = rsqrtf(var + 1e-5f);
    }
    __syncthreads();
    const float mu = smu, inv = sinv;
#pragma unroll
    for (int i = 0; i < 4; i++) {
        const int c = tid + 256 * i;
        const float o = (v[i] - mu) * inv * g[c] + be[c];
        out[(size_t)row * D_ + c] = o;
        if (hi) hi[(size_t)row * D_ + c] = __float2half_rn(o);
    }
}

// ---------------- launch ----------------
extern "C" void kernel_launch(void* const* d_in, const int* in_sizes, int n_in,
                              void* d_out, int out_size) {
    const float* src    = (const float*)d_in[0];
    const int*   coords = (const int*)  d_in[1];
    const float* Wq = (const float*)d_in[2];
    const float* Wk = (const float*)d_in[3];
    const float* Wv = (const float*)d_in[4];
    const float* Wo = (const float*)d_in[5];
    const float* W1 = (const float*)d_in[6];
    const float* b1 = (const float*)d_in[7];
    const float* W2 = (const float*)d_in[8];
    const float* b2 = (const float*)d_in[9];
    const float* g1 = (const float*)d_in[10];
    const float* be1= (const float*)d_in[11];
    const float* g2 = (const float*)d_in[12];
    const float* be2= (const float*)d_in[13];
    float* out = (float*)d_out;

    void *pt, *px;
    cudaGetSymbolAddress(&pt, g_t);
    cudaGetSymbolAddress(&px, g_x);

    void *srch,*wqh,*wql,*wkh,*wkl,*wvh,*wvl,*woh,*wol,*w1h,*w1l,*w2h,*w2l;
    void *xh,*aoh,*ffh,*qhh,*khh,*kll,*vhh;
    cudaGetSymbolAddress(&srch, s_src_h);
    cudaGetSymbolAddress(&wqh, s_wq_h);   cudaGetSymbolAddress(&wql, s_wq_l);
    cudaGetSymbolAddress(&wkh, s_wk_h);   cudaGetSymbolAddress(&wkl, s_wk_l);
    cudaGetSymbolAddress(&wvh, s_wv_h);   cudaGetSymbolAddress(&wvl, s_wv_l);
    cudaGetSymbolAddress(&woh, s_wo_h);   cudaGetSymbolAddress(&wol, s_wo_l);
    cudaGetSymbolAddress(&w1h, s_w1_h);   cudaGetSymbolAddress(&w1l, s_w1_l);
    cudaGetSymbolAddress(&w2h, s_w2_h);   cudaGetSymbolAddress(&w2l, s_w2_l);
    cudaGetSymbolAddress(&xh,  s_x_h);
    cudaGetSymbolAddress(&aoh, s_ao_h);
    cudaGetSymbolAddress(&ffh, s_ff_h);
    cudaGetSymbolAddress(&qhh, s_q_h);
    cudaGetSymbolAddress(&khh, s_k_h);    cudaGetSymbolAddress(&kll, s_k_l);
    cudaGetSymbolAddress(&vhh, s_v_h);

    cudaFuncSetAttribute((const void*)mma_gemm<0, 0, 2>,
                         cudaFuncAttributeMaxDynamicSharedMemorySize, GEMM_SMEM_BYTES);
    cudaFuncSetAttribute((const void*)mma_gemm<1, 1, 2>,
                         cudaFuncAttributeMaxDynamicSharedMemorySize, GEMM_SMEM_BYTES);
    cudaFuncSetAttribute((const void*)qkv_gemm,
                         cudaFuncAttributeMaxDynamicSharedMemorySize, GEMM_SMEM_BYTES);
    cudaFuncSetAttribute((const void*)attn_mma_kernel,
                         cudaFuncAttributeMaxDynamicSharedMemorySize, ATT_SMEM);

    const int nSrc4 = M_ * D_ / 4;
    const int nW4   = D_ * D_ / 4;
    const int nW14  = FF_ * D_ / 4;

    const dim3 blk(256);
    const dim3 gD(D_ / 128, M_ / 128);        // (8, 32)
    const dim3 gQKV(D_ / 128, M_ / 128, 3);   // (8, 32, 3)
    const dim3 gF(FF_ / 128, M_ / 128);       // (32, 32)

    // splits (src: hi only)
    split_kernel<<<nSrc4 / 256, 256>>>((const float4*)src, (uint2*)srch, nullptr, nSrc4);
    split_kernel<<<nW4 / 256, 256>>>((const float4*)Wq, (uint2*)wqh, (uint2*)wql, nW4);
    split_kernel<<<nW4 / 256, 256>>>((const float4*)Wk, (uint2*)wkh, (uint2*)wkl, nW4);
    split_kernel<<<nW4 / 256, 256>>>((const float4*)Wv, (uint2*)wvh, (uint2*)wvl, nW4);

    // fused QKV projections (2-term; K hi/lo, Q/V hi only)
    qkv_gemm<<<gQKV, blk, GEMM_SMEM_BYTES>>>(
        (const __half*)srch,
        (const __half*)wqh,  (const __half*)wql,
        (const __half*)wkh,  (const __half*)wkl,
        (const __half*)wvh,  (const __half*)wvl,
        (__half*)qhh,
        (__half*)khh, (__half*)kll,
        (__half*)vhh);

    // remaining weight splits
    split_kernel<<<nW4 / 256, 256>>>((const float4*)Wo, (uint2*)woh, (uint2*)wol, nW4);
    split_kernel<<<nW14 / 256, 256>>>((const float4*)W1, (uint2*)w1h, (uint2*)w1l, nW14);
    split_kernel<<<nW14 / 256, 256>>>((const float4*)W2, (uint2*)w2h, (uint2*)w2l, nW14);

    // flash attention (2-term fp16)
    attn_mma_kernel<<<512, 256, ATT_SMEM>>>(
        (const __half*)qhh,
        (const __half*)khh, (const __half*)kll,
        (const __half*)vhh,
        coords, (__half*)aoh);

    // output projection (2-term: ao plain, Wo split) -> fp32 t ; residual + LN1 -> x
    mma_gemm<0, 0, 2><<<gD, blk, GEMM_SMEM_BYTES>>>(
        (const __half*)aoh, nullptr,
        (const __half*)woh, (const __half*)wol,
        nullptr, (float*)pt, nullptr, nullptr, D_, D_);
    add_ln_kernel<<<M_, 256>>>(src, (const float*)pt, g1, be1, (float*)px, (__half*)xh);

    // FFN1 (2-term; bias + exact gelu; plain fp16 out)
    mma_gemm<1, 1, 2><<<gF, blk, GEMM_SMEM_BYTES>>>(
        (const __half*)xh,  nullptr,
        (const __half*)w1h, (const __half*)w1l,
        b1, nullptr, (__half*)ffh, nullptr, FF_, D_);

    // FFN2 (2-term; bias; fp32 out) ; residual + LN2 -> out
    mma_gemm<0, 0, 2><<<gD, blk, GEMM_SMEM_BYTES>>>(
        (const __half*)ffh, nullptr,
        (const __half*)w2h, (const __half*)w2l,
        b2, (float*)pt, nullptr, nullptr, D_, FF_);
    add_ln_kernel<<<M_, 256>>>((const float*)px, (const float*)pt, g2, be2, out, nullptr);
}

// round 11
// speedup vs baseline: 2.1200x; 1.5236x over previous
#include <cuda_runtime.h>
#include <cuda_fp16.h>
#include <math.h>
#include <stdint.h>

#define B_   4
#define N_   1024
#define D_   1024
#define H_   16
#define HD_  64
#define FF_  4096
#define M_   (B_ * N_)   // 4096 rows

// ---------------- scratch (static device globals; no allocs allowed) ----------------
__device__ float g_t [M_ * D_];   // src2 / ffn2 output temp (fp32)
__device__ float g_x [M_ * D_];   // post-LN1 activations (fp32)

// plain fp16 buffers
__device__ __half s_src_h[M_ * D_];
__device__ __half s_wq_h [D_ * D_];
__device__ __half s_wk_h [D_ * D_];
__device__ __half s_wv_h [D_ * D_];
__device__ __half s_wo_h [D_ * D_];
__device__ __half s_w1_h [FF_ * D_];
__device__ __half s_w2_h [D_ * FF_];
__device__ __half s_x_h  [M_ * D_];
__device__ __half s_ao_h [M_ * D_];
__device__ __half s_ff_h [M_ * FF_];
__device__ __half s_q_h  [M_ * D_];
__device__ __half s_k_h  [M_ * D_];
__device__ __half s_v_h  [M_ * D_];

// ---------------- PTX helpers (Ampere-era only: valid at compute_103 base) ----------
__device__ __forceinline__ uint32_t s2u(const void* p) {
    uint32_t a;
    asm("{ .reg .u64 t; cvta.to.shared.u64 t, %1; cvt.u32.u64 %0, t; }" : "=r"(a) : "l"(p));
    return a;
}
__device__ __forceinline__ void cp_async16(uint32_t saddr, const void* g) {
    asm volatile("cp.async.cg.shared.global [%0], [%1], 16;" :: "r"(saddr), "l"(g) : "memory");
}
#define CP_COMMIT()  asm volatile("cp.async.commit_group;" ::: "memory")
#define CP_WAIT(n)   asm volatile("cp.async.wait_group %0;" :: "n"(n) : "memory")

__device__ __forceinline__ void ldsm4(uint32_t* r, uint32_t addr) {
    asm volatile("ldmatrix.sync.aligned.m8n8.x4.shared.b16 {%0,%1,%2,%3}, [%4];"
                 : "=r"(r[0]), "=r"(r[1]), "=r"(r[2]), "=r"(r[3]) : "r"(addr));
}
__device__ __forceinline__ void ldsm4t(uint32_t* r, uint32_t addr) {
    asm volatile("ldmatrix.sync.aligned.m8n8.x4.trans.shared.b16 {%0,%1,%2,%3}, [%4];"
                 : "=r"(r[0]), "=r"(r[1]), "=r"(r[2]), "=r"(r[3]) : "r"(addr));
}
__device__ __forceinline__ void mma16816(float* c, const uint32_t* a, const uint32_t* b) {
    asm volatile(
        "mma.sync.aligned.m16n8k16.row.col.f32.f16.f16.f32 "
        "{%0,%1,%2,%3}, {%4,%5,%6,%7}, {%8,%9}, {%0,%1,%2,%3};"
        : "+f"(c[0]), "+f"(c[1]), "+f"(c[2]), "+f"(c[3])
        : "r"(a[0]), "r"(a[1]), "r"(a[2]), "r"(a[3]), "r"(b[0]), "r"(b[1]));
}

#define SWZ(o) ((o) ^ (((o) >> 3) & 0x70))

__device__ __forceinline__ uint32_t pack_h(float a, float b) {
    __half2 hp = __halves2half2(__float2half_rn(a), __float2half_rn(b));
    return *(uint32_t*)&hp;
}

// ---------------- convert fp32 -> fp16 ----------------
__global__ __launch_bounds__(256)
void cvt_kernel(const float4* __restrict__ x, uint2* __restrict__ hi, int n4) {
    int i = blockIdx.x * 256 + threadIdx.x;
    if (i >= n4) return;
    float4 v = x[i];
    hi[i] = make_uint2(pack_h(v.x, v.y), pack_h(v.z, v.w));
}

// ---------------- HMMA GEMM: C[M,Nn] = A[M,K] @ W[Nn,K]^T, plain fp16 ---------------
// 128x128 tile, 256 thr, warptile 64x32, BK=64, 3-stage cp.async.
// stage: Ah[0,16K) Wh[16K,32K) -> 32KB/stage
#define STAGE_BYTES 32768
#define GEMM_STAGES 3
#define GEMM_SMEM_BYTES (GEMM_STAGES * STAGE_BYTES)

template <int ACT, int OUTMODE>
__device__ __forceinline__
void gemm_body(const __half* __restrict__ Ah, const __half* __restrict__ Wh,
               const float* __restrict__ bias,
               float* __restrict__ Cf, __half* __restrict__ Ch,
               int Nn, int K, int mBase, int nBase, char* dsm) {
    const uint32_t sb = s2u(dsm);

    const int tid  = threadIdx.x;
    const int wid  = tid >> 5;
    const int lane = tid & 31;
    const int wm   = wid & 1;        // 2 warps in m (64 rows each)
    const int wn   = wid >> 1;       // 4 warps in n (32 cols each)
    const int NC = K / 64;

    const int r0 = tid >> 3;
    const int c0 = tid & 7;

    const __half* pAh = Ah + (size_t)(mBase + r0) * K + c0 * 8;
    const __half* pWh = Wh + (size_t)(nBase + r0) * K + c0 * 8;

    auto load_stage = [&](int buf, int kcol) {
        const uint32_t stage = sb + buf * STAGE_BYTES;
#pragma unroll
        for (int j = 0; j < 4; j++) {
            const int r = r0 + 32 * j;
            const uint32_t off = SWZ((uint32_t)(r * 128 + c0 * 16));
            cp_async16(stage + off,         pAh + (size_t)(32 * j) * K + kcol);
            cp_async16(stage + 16384 + off, pWh + (size_t)(32 * j) * K + kcol);
        }
    };

    float acc[4][4][4];
#pragma unroll
    for (int i = 0; i < 4; i++)
#pragma unroll
        for (int j = 0; j < 4; j++)
#pragma unroll
            for (int t = 0; t < 4; t++) acc[i][j][t] = 0.f;

    const int aRow = wm * 64 + (lane & 15);
    const int aColSel = (lane >> 4) * 8;
    const int bRow = wn * 32 + ((lane >> 4) << 3) + (lane & 7);
    const int bColSel = ((lane >> 3) & 1) * 8;

    load_stage(0, 0);
    CP_COMMIT();
    load_stage(1, 64);
    CP_COMMIT();

    for (int c = 0; c < NC; c++) {
        if (c + 2 < NC) { CP_WAIT(1); }
        else            { CP_WAIT(0); }
        __syncthreads();

        const uint32_t stage = sb + (c % GEMM_STAGES) * STAGE_BYTES;
        const uint32_t sAh = stage, sWh = stage + 16384;

#pragma unroll
        for (int ks = 0; ks < 4; ks++) {
            const int kc = ks * 16;
            uint32_t ah[4][4];
#pragma unroll
            for (int fm = 0; fm < 4; fm++) {
                const uint32_t off = SWZ((uint32_t)((aRow + fm * 16) * 128 + (kc + aColSel) * 2));
                ldsm4(ah[fm], sAh + off);
            }
            uint32_t bh[4][2];
#pragma unroll
            for (int ng = 0; ng < 2; ng++) {
                const uint32_t off = SWZ((uint32_t)((bRow + ng * 16) * 128 + (kc + bColSel) * 2));
                uint32_t t[4];
                ldsm4(t, sWh + off);
                bh[ng*2][0] = t[0]; bh[ng*2][1] = t[1];
                bh[ng*2+1][0] = t[2]; bh[ng*2+1][1] = t[3];
            }
#pragma unroll
            for (int fm = 0; fm < 4; fm++)
#pragma unroll
                for (int fn = 0; fn < 4; fn++)
                    mma16816(acc[fm][fn], ah[fm], bh[fn]);
        }
        __syncthreads();

        if (c + 2 < NC) {
            load_stage((c + 2) % GEMM_STAGES, (c + 2) * 64);
            CP_COMMIT();
        }
    }

    // ---- epilogue ----
    const int erow = mBase + wm * 64 + (lane >> 2);
    const int ecol = nBase + wn * 32 + (lane & 3) * 2;
#pragma unroll
    for (int fm = 0; fm < 4; fm++) {
#pragma unroll
        for (int fn = 0; fn < 4; fn++) {
            const int col = ecol + fn * 8;
#pragma unroll
            for (int half = 0; half < 2; half++) {
                const int row = erow + fm * 16 + half * 8;
                float v0 = acc[fm][fn][half * 2 + 0];
                float v1 = acc[fm][fn][half * 2 + 1];
                if (bias) { v0 += bias[col]; v1 += bias[col + 1]; }
                if (ACT == 1) {
                    v0 = 0.5f * v0 * (1.f + erff(v0 * 0.70710678118654752f));
                    v1 = 0.5f * v1 * (1.f + erff(v1 * 0.70710678118654752f));
                }
                const size_t base = (size_t)row * Nn + col;
                if (OUTMODE == 1) {
                    *(uint32_t*)(Ch + base) = pack_h(v0, v1);
                } else {
                    *(float2*)(Cf + base) = make_float2(v0, v1);
                }
            }
        }
    }
}

template <int ACT, int OUTMODE>
__global__ __launch_bounds__(256, 1)
void mma_gemm(const __half* __restrict__ Ah, const __half* __restrict__ Wh,
              const float* __restrict__ bias,
              float* __restrict__ Cf, __half* __restrict__ Ch,
              int Nn, int K) {
    extern __shared__ char dsm[];
    gemm_body<ACT, OUTMODE>(Ah, Wh, bias, Cf, Ch,
                            Nn, K, blockIdx.y * 128, blockIdx.x * 128, dsm);
}

// fused QKV: gridDim.z selects which projection this CTA computes
__global__ __launch_bounds__(256, 1)
void qkv_gemm(const __half* __restrict__ Ah,
              const __half* __restrict__ Wq, const __half* __restrict__ Wk,
              const __half* __restrict__ Wv,
              __half* __restrict__ Cq, __half* __restrict__ Ck,
              __half* __restrict__ Cv) {
    extern __shared__ char dsm[];
    const int z = blockIdx.z;
    const __half* Wh = (z == 0) ? Wq : (z == 1) ? Wk : Wv;
    __half* Ch = (z == 0) ? Cq : (z == 1) ? Ck : Cv;
    gemm_body<0, 1>(Ah, Wh, nullptr, nullptr, Ch,
                    D_, D_, blockIdx.y * 128, blockIdx.x * 128, dsm);
}

// ---------------- flash attention, plain fp16: S=QK^T, O=PV -------------------------
// smem: Q[0,16K), stages at 16384 + s*16896: Kh +0, Vh +8192, coords +16384
#define ATT_STAGE 16896
#define ATT_SMEM  (16384 + 2 * ATT_STAGE)

__global__ __launch_bounds__(256, 1)
void attn_mma_kernel(const __half* __restrict__ qh,
                     const __half* __restrict__ kh,
                     const __half* __restrict__ vh,
                     const int* __restrict__ coords,
                     __half* __restrict__ aoh) {
    extern __shared__ char dsm[];
    const uint32_t sb = s2u(dsm);

    const int tid  = threadIdx.x;
    const int wid  = tid >> 5;
    const int lane = tid & 31;
    const int qt = blockIdx.x & 7;
    const int h  = (blockIdx.x >> 3) & 15;
    const int b  = blockIdx.x >> 7;
    const int qbase = qt * 128;

    const float slope = exp2f(-0.5f * (float)(h + 1));
    const float scale = 0.125f;

    const int r0 = wid * 16 + (lane >> 2);
    const int grow0 = b * N_ + qbase + r0;
    const float xi0 = (float)coords[grow0 * 2 + 0];
    const float yi0 = (float)coords[grow0 * 2 + 1];
    const float xi1 = (float)coords[(grow0 + 8) * 2 + 0];
    const float yi1 = (float)coords[(grow0 + 8) * 2 + 1];

    {   // Q (plain fp16, 16 KB)
        const int rr = tid >> 3, cc = tid & 7;
#pragma unroll
        for (int j = 0; j < 4; j++) {
            const int r = rr + 32 * j;
            const size_t go = (size_t)(b * N_ + qbase + r) * D_ + h * HD_ + cc * 8;
            cp_async16(sb + SWZ((uint32_t)(r * 128 + cc * 16)), qh + go);
        }
    }
    CP_COMMIT();

    auto load_kv = [&](int t, int buf) {
        const uint32_t st = sb + 16384 + buf * ATT_STAGE;
        const int kt = t * 64;
        const int rr = tid >> 2, cc = tid & 3;
        const size_t gbase = (size_t)(b * N_ + kt) * D_ + h * HD_;
#pragma unroll
        for (int j = 0; j < 2; j++) {
            const int ch = cc + 4 * j;
            const uint32_t off = SWZ((uint32_t)(rr * 128 + ch * 16));
            cp_async16(st + off,        kh + gbase + (size_t)rr * D_ + ch * 8);
            cp_async16(st + 8192 + off, vh + gbase + (size_t)rr * D_ + ch * 8);
        }
        if (tid < 32)
            cp_async16(st + 16384 + tid * 16,
                       (const char*)coords + (size_t)(b * N_ + kt) * 8 + tid * 16);
    };

    load_kv(0, 0);
    CP_COMMIT();

    float m0 = -1e30f, m1 = -1e30f, l0 = 0.f, l1 = 0.f;
    float acc_o[8][4];
#pragma unroll
    for (int f = 0; f < 8; f++)
#pragma unroll
        for (int t = 0; t < 4; t++) acc_o[f][t] = 0.f;

    const int aRow  = wid * 16 + (lane & 15);
    const int aCol  = (lane >> 4) * 8;
    const int bRowK = ((lane >> 4) << 3) + (lane & 7);
    const int bColK = ((lane >> 3) & 1) * 8;
    const int vRow  = ((lane >> 3) & 1) * 8 + (lane & 7);
    const int vCol  = (lane >> 4) * 8;

    for (int t = 0; t < 16; t++) {
        const int buf = t & 1;
        if (t + 1 < 16) { load_kv(t + 1, 1 - buf); CP_COMMIT(); CP_WAIT(1); }
        else            { CP_WAIT(0); }
        __syncthreads();

        const uint32_t st = sb + 16384 + buf * ATT_STAGE;
        const uint32_t sKh = st, sVh = st + 8192;
        const int2* kco = (const int2*)(dsm + 16384 + buf * ATT_STAGE + 16384);

        float accs[8][4];
#pragma unroll
        for (int f = 0; f < 8; f++)
#pragma unroll
            for (int u = 0; u < 4; u++) accs[f][u] = 0.f;

#pragma unroll
        for (int ks = 0; ks < 4; ks++) {
            const int kc = ks * 16;
            uint32_t ah[4];
            ldsm4(ah, sb + SWZ((uint32_t)(aRow * 128 + (kc + aCol) * 2)));
#pragma unroll
            for (int nh = 0; nh < 4; nh++) {
                const uint32_t boff = SWZ((uint32_t)((nh * 16 + bRowK) * 128 + (kc + bColK) * 2));
                uint32_t tb[4];
                ldsm4(tb, sKh + boff);
                uint32_t bh0[2] = { tb[0], tb[1] }, bh1[2] = { tb[2], tb[3] };
                mma16816(accs[nh*2],   ah, bh0);
                mma16816(accs[nh*2+1], ah, bh1);
            }
        }

#pragma unroll
        for (int f = 0; f < 8; f++) {
            const int c = f * 8 + (lane & 3) * 2;
            const int2 ca = kco[c], cb = kco[c + 1];
            const float xa = (float)ca.x, ya = (float)ca.y;
            const float xb = (float)cb.x, yb = (float)cb.y;
            accs[f][0] = fmaf(accs[f][0], scale, slope * (fabsf(xi0 - xa) + fabsf(yi0 - ya)));
            accs[f][1] = fmaf(accs[f][1], scale, slope * (fabsf(xi0 - xb) + fabsf(yi0 - yb)));
            accs[f][2] = fmaf(accs[f][2], scale, slope * (fabsf(xi1 - xa) + fabsf(yi1 - ya)));
            accs[f][3] = fmaf(accs[f][3], scale, slope * (fabsf(xi1 - xb) + fabsf(yi1 - yb)));
        }

        float mx0 = -1e30f, mx1 = -1e30f;
#pragma unroll
        for (int f = 0; f < 8; f++) {
            mx0 = fmaxf(mx0, fmaxf(accs[f][0], accs[f][1]));
            mx1 = fmaxf(mx1, fmaxf(accs[f][2], accs[f][3]));
        }
        mx0 = fmaxf(mx0, __shfl_xor_sync(0xffffffffu, mx0, 1));
        mx0 = fmaxf(mx0, __shfl_xor_sync(0xffffffffu, mx0, 2));
        mx1 = fmaxf(mx1, __shfl_xor_sync(0xffffffffu, mx1, 1));
        mx1 = fmaxf(mx1, __shfl_xor_sync(0xffffffffu, mx1, 2));
        const float nm0 = fmaxf(m0, mx0), nm1 = fmaxf(m1, mx1);
        const float cr0 = __expf(m0 - nm0), cr1 = __expf(m1 - nm1);
        m0 = nm0; m1 = nm1;
        l0 *= cr0; l1 *= cr1;
#pragma unroll
        for (int f = 0; f < 8; f++) {
            acc_o[f][0] *= cr0; acc_o[f][1] *= cr0;
            acc_o[f][2] *= cr1; acc_o[f][3] *= cr1;
        }
#pragma unroll
        for (int f = 0; f < 8; f++) {
            accs[f][0] = __expf(accs[f][0] - nm0);
            accs[f][1] = __expf(accs[f][1] - nm0);
            accs[f][2] = __expf(accs[f][2] - nm1);
            accs[f][3] = __expf(accs[f][3] - nm1);
            l0 += accs[f][0] + accs[f][1];
            l1 += accs[f][2] + accs[f][3];
        }

        // ---- O += P Vh (plain fp16 P) ----
#pragma unroll
        for (int kg = 0; kg < 4; kg++) {
            const float* s0 = accs[2 * kg];
            const float* s1 = accs[2 * kg + 1];
            uint32_t pa[4];
            pa[0] = pack_h(s0[0], s0[1]);
            pa[1] = pack_h(s0[2], s0[3]);
            pa[2] = pack_h(s1[0], s1[1]);
            pa[3] = pack_h(s1[2], s1[3]);
#pragma unroll
            for (int vi = 0; vi < 4; vi++) {
                const uint32_t voff =
                    SWZ((uint32_t)((kg * 16 + vRow) * 128 + (vi * 16 + vCol) * 2));
                uint32_t tv[4];
                ldsm4t(tv, sVh + voff);
                uint32_t bvh0[2] = { tv[0], tv[1] }, bvh1[2] = { tv[2], tv[3] };
                mma16816(acc_o[vi*2],   pa, bvh0);
                mma16816(acc_o[vi*2+1], pa, bvh1);
            }
        }
        __syncthreads();
    }

    l0 += __shfl_xor_sync(0xffffffffu, l0, 1);
    l0 += __shfl_xor_sync(0xffffffffu, l0, 2);
    l1 += __shfl_xor_sync(0xffffffffu, l1, 1);
    l1 += __shfl_xor_sync(0xffffffffu, l1, 2);
    const float inv0 = 1.f / l0, inv1 = 1.f / l1;
#pragma unroll
    for (int f = 0; f < 8; f++) {
        const int c = f * 8 + (lane & 3) * 2;
        const size_t base0 = (size_t)grow0 * D_ + h * HD_ + c;
        const size_t base1 = (size_t)(grow0 + 8) * D_ + h * HD_ + c;
        *(uint32_t*)(aoh + base0) = pack_h(acc_o[f][0] * inv0, acc_o[f][1] * inv0);
        *(uint32_t*)(aoh + base1) = pack_h(acc_o[f][2] * inv1, acc_o[f][3] * inv1);
    }
}

// ---------------- fused residual add + LayerNorm (+ optional plain fp16 emit) -------
__global__ __launch_bounds__(256)
void add_ln_kernel(const float* __restrict__ a, const float* __restrict__ bsum,
                   const float* __restrict__ g, const float* __restrict__ be,
                   float* __restrict__ out, __half* __restrict__ hi) {
    const int row = blockIdx.x;
    const int tid = threadIdx.x;
    const float* pa = a    + (size_t)row * D_;
    const float* pb = bsum + (size_t)row * D_;

    float v[4];
    float s = 0.f, ss = 0.f;
#pragma unroll
    for (int i = 0; i < 4; i++) {
        const int c = tid + 256 * i;
        const float t = pa[c] + pb[c];
        v[i] = t; s += t; ss = fmaf(t, t, ss);
    }
#pragma unroll
    for (int o = 16; o > 0; o >>= 1) {
        s  += __shfl_xor_sync(0xffffffffu, s,  o);
        ss += __shfl_xor_sync(0xffffffffu, ss, o);
    }
    __shared__ float rs[8], rss[8];
    __shared__ float smu, sinv;
    const int w = tid >> 5;
    if ((tid & 31) == 0) { rs[w] = s; rss[w] = ss; }
    __syncthreads();
    if (tid == 0) {
        float S = 0.f, SS = 0.f;
#pragma unroll
        for (int i = 0; i < 8; i++) { S += rs[i]; SS += rss[i]; }
        const float mu  = S * (1.f / 1024.f);
        const float var = SS * (1.f / 1024.f) - mu * mu;
        smu = mu; sinv = rsqrtf(var + 1e-5f);
    }
    __syncthreads();
    const float mu = smu, inv = sinv;
#pragma unroll
    for (int i = 0; i < 4; i++) {
        const int c = tid + 256 * i;
        const float o = (v[i] - mu) * inv * g[c] + be[c];
        out[(size_t)row * D_ + c] = o;
        if (hi) hi[(size_t)row * D_ + c] = __float2half_rn(o);
    }
}

// ---------------- launch ----------------
extern "C" void kernel_launch(void* const* d_in, const int* in_sizes, int n_in,
                              void* d_out, int out_size) {
    const float* src    = (const float*)d_in[0];
    const int*   coords = (const int*)  d_in[1];
    const float* Wq = (const float*)d_in[2];
    const float* Wk = (const float*)d_in[3];
    const float* Wv = (const float*)d_in[4];
    const float* Wo = (const float*)d_in[5];
    const float* W1 = (const float*)d_in[6];
    const float* b1 = (const float*)d_in[7];
    const float* W2 = (const float*)d_in[8];
    const float* b2 = (const float*)d_in[9];
    const float* g1 = (const float*)d_in[10];
    const float* be1= (const float*)d_in[11];
    const float* g2 = (const float*)d_in[12];
    const float* be2= (const float*)d_in[13];
    float* out = (float*)d_out;

    void *pt, *px;
    cudaGetSymbolAddress(&pt, g_t);
    cudaGetSymbolAddress(&px, g_x);

    void *srch,*wqh,*wkh,*wvh,*woh,*w1h,*w2h;
    void *xh,*aoh,*ffh,*qhh,*khh,*vhh;
    cudaGetSymbolAddress(&srch, s_src_h);
    cudaGetSymbolAddress(&wqh, s_wq_h);
    cudaGetSymbolAddress(&wkh, s_wk_h);
    cudaGetSymbolAddress(&wvh, s_wv_h);
    cudaGetSymbolAddress(&woh, s_wo_h);
    cudaGetSymbolAddress(&w1h, s_w1_h);
    cudaGetSymbolAddress(&w2h, s_w2_h);
    cudaGetSymbolAddress(&xh,  s_x_h);
    cudaGetSymbolAddress(&aoh, s_ao_h);
    cudaGetSymbolAddress(&ffh, s_ff_h);
    cudaGetSymbolAddress(&qhh, s_q_h);
    cudaGetSymbolAddress(&khh, s_k_h);
    cudaGetSymbolAddress(&vhh, s_v_h);

    cudaFuncSetAttribute((const void*)mma_gemm<0, 0>,
                         cudaFuncAttributeMaxDynamicSharedMemorySize, GEMM_SMEM_BYTES);
    cudaFuncSetAttribute((const void*)mma_gemm<0, 1>,
                         cudaFuncAttributeMaxDynamicSharedMemorySize, GEMM_SMEM_BYTES);
    cudaFuncSetAttribute((const void*)mma_gemm<1, 1>,
                         cudaFuncAttributeMaxDynamicSharedMemorySize, GEMM_SMEM_BYTES);
    cudaFuncSetAttribute((const void*)qkv_gemm,
                         cudaFuncAttributeMaxDynamicSharedMemorySize, GEMM_SMEM_BYTES);
    cudaFuncSetAttribute((const void*)attn_mma_kernel,
                         cudaFuncAttributeMaxDynamicSharedMemorySize, ATT_SMEM);

    const int nSrc4 = M_ * D_ / 4;
    const int nW4   = D_ * D_ / 4;
    const int nW14  = FF_ * D_ / 4;

    const dim3 blk(256);
    const dim3 gD(D_ / 128, M_ / 128);        // (8, 32)
    const dim3 gQKV(D_ / 128, M_ / 128, 3);   // (8, 32, 3)
    const dim3 gF(FF_ / 128, M_ / 128);       // (32, 32)

    // converts
    cvt_kernel<<<nSrc4 / 256, 256>>>((const float4*)src, (uint2*)srch, nSrc4);
    cvt_kernel<<<nW4 / 256, 256>>>((const float4*)Wq, (uint2*)wqh, nW4);
    cvt_kernel<<<nW4 / 256, 256>>>((const float4*)Wk, (uint2*)wkh, nW4);
    cvt_kernel<<<nW4 / 256, 256>>>((const float4*)Wv, (uint2*)wvh, nW4);

    // fused QKV projections
    qkv_gemm<<<gQKV, blk, GEMM_SMEM_BYTES>>>(
        (const __half*)srch,
        (const __half*)wqh, (const __half*)wkh, (const __half*)wvh,
        (__half*)qhh, (__half*)khh, (__half*)vhh);

    // remaining weight converts
    cvt_kernel<<<nW4 / 256, 256>>>((const float4*)Wo, (uint2*)woh, nW4);
    cvt_kernel<<<nW14 / 256, 256>>>((const float4*)W1, (uint2*)w1h, nW14);
    cvt_kernel<<<nW14 / 256, 256>>>((const float4*)W2, (uint2*)w2h, nW14);

    // flash attention
    attn_mma_kernel<<<512, 256, ATT_SMEM>>>(
        (const __half*)qhh, (const __half*)khh, (const __half*)vhh,
        coords, (__half*)aoh);

    // output projection -> fp32 t ; residual + LN1 -> x (fp32 + plain fp16)
    mma_gemm<0, 0><<<gD, blk, GEMM_SMEM_BYTES>>>(
        (const __half*)aoh, (const __half*)woh,
        nullptr, (float*)pt, nullptr, D_, D_);
    add_ln_kernel<<<M_, 256>>>(src, (const float*)pt, g1, be1, (float*)px, (__half*)xh);

    // FFN1 (bias + exact gelu; plain fp16 out)
    mma_gemm<1, 1><<<gF, blk, GEMM_SMEM_BYTES>>>(
        (const __half*)xh, (const __half*)w1h,
        b1, nullptr, (__half*)ffh, FF_, D_);

    // FFN2 (bias; fp32 out) ; residual + LN2 -> out
    mma_gemm<0, 0><<<gD, blk, GEMM_SMEM_BYTES>>>(
        (const __half*)ffh, (const __half*)w2h,
        b2, (float*)pt, nullptr, D_, FF_);
    add_ln_kernel<<<M_, 256>>>((const float*)px, (const float*)pt, g2, be2, out, nullptr);
}

// round 12
// speedup vs baseline: 2.5166x; 1.1871x over previous
#include <cuda_runtime.h>
#include <cuda_fp16.h>
#include <math.h>
#include <stdint.h>

#define B_   4
#define N_   1024
#define D_   1024
#define H_   16
#define HD_  64
#define FF_  4096
#define M_   (B_ * N_)   // 4096 rows

// ---------------- scratch (static device globals; no allocs allowed) ----------------
__device__ float g_t [M_ * D_];   // src2 / ffn2 output temp (fp32)
__device__ float g_x [M_ * D_];   // post-LN1 activations (fp32)

// plain fp16 buffers
__device__ __half s_src_h[M_ * D_];
__device__ __half s_wq_h [D_ * D_];
__device__ __half s_wk_h [D_ * D_];
__device__ __half s_wv_h [D_ * D_];
__device__ __half s_wo_h [D_ * D_];
__device__ __half s_w1_h [FF_ * D_];
__device__ __half s_w2_h [D_ * FF_];
__device__ __half s_x_h  [M_ * D_];
__device__ __half s_ao_h [M_ * D_];
__device__ __half s_ff_h [M_ * FF_];
__device__ __half s_q_h  [M_ * D_];
__device__ __half s_k_h  [M_ * D_];
__device__ __half s_v_h  [M_ * D_];

// ---------------- PTX helpers (Ampere-era only: valid at compute_103 base) ----------
__device__ __forceinline__ uint32_t s2u(const void* p) {
    uint32_t a;
    asm("{ .reg .u64 t; cvta.to.shared.u64 t, %1; cvt.u32.u64 %0, t; }" : "=r"(a) : "l"(p));
    return a;
}
__device__ __forceinline__ void cp_async16(uint32_t saddr, const void* g) {
    asm volatile("cp.async.cg.shared.global [%0], [%1], 16;" :: "r"(saddr), "l"(g) : "memory");
}
#define CP_COMMIT()  asm volatile("cp.async.commit_group;" ::: "memory")
#define CP_WAIT(n)   asm volatile("cp.async.wait_group %0;" :: "n"(n) : "memory")

__device__ __forceinline__ void ldsm4(uint32_t* r, uint32_t addr) {
    asm volatile("ldmatrix.sync.aligned.m8n8.x4.shared.b16 {%0,%1,%2,%3}, [%4];"
                 : "=r"(r[0]), "=r"(r[1]), "=r"(r[2]), "=r"(r[3]) : "r"(addr));
}
__device__ __forceinline__ void ldsm4t(uint32_t* r, uint32_t addr) {
    asm volatile("ldmatrix.sync.aligned.m8n8.x4.trans.shared.b16 {%0,%1,%2,%3}, [%4];"
                 : "=r"(r[0]), "=r"(r[1]), "=r"(r[2]), "=r"(r[3]) : "r"(addr));
}
__device__ __forceinline__ void mma16816(float* c, const uint32_t* a, const uint32_t* b) {
    asm volatile(
        "mma.sync.aligned.m16n8k16.row.col.f32.f16.f16.f32 "
        "{%0,%1,%2,%3}, {%4,%5,%6,%7}, {%8,%9}, {%0,%1,%2,%3};"
        : "+f"(c[0]), "+f"(c[1]), "+f"(c[2]), "+f"(c[3])
        : "r"(a[0]), "r"(a[1]), "r"(a[2]), "r"(a[3]), "r"(b[0]), "r"(b[1]));
}

#define SWZ(o) ((o) ^ (((o) >> 3) & 0x70))

__device__ __forceinline__ uint32_t pack_h(float a, float b) {
    __half2 hp = __halves2half2(__float2half_rn(a), __float2half_rn(b));
    return *(uint32_t*)&hp;
}

// ---------------- batched convert fp32 -> fp16 (all 7 tensors, one launch) ----------
#define CVT_JOBS 7
struct CvtJobs {
    const float4* src[CVT_JOBS];
    uint2*        dst[CVT_JOBS];
    int           prefix[CVT_JOBS + 1];  // block prefix sums
};

__global__ __launch_bounds__(256)
void cvt_all_kernel(CvtJobs jobs) {
    const int blk = blockIdx.x;
    int j = 0;
#pragma unroll
    for (int k = 1; k < CVT_JOBS; k++)
        if (blk >= jobs.prefix[k]) j = k;
    const int i = (blk - jobs.prefix[j]) * 256 + threadIdx.x;
    const int n4 = (jobs.prefix[j + 1] - jobs.prefix[j]) * 256;
    if (i >= n4) return;
    float4 v = jobs.src[j][i];
    jobs.dst[j][i] = make_uint2(pack_h(v.x, v.y), pack_h(v.z, v.w));
}

// ---------------- HMMA GEMM: C[M,Nn] = A[M,K] @ W[Nn,K]^T, plain fp16 ---------------
// 128x128 tile, 256 thr, warptile 64x32, BK=64, 3-stage cp.async, 2 CTAs/SM.
#define STAGE_BYTES 32768
#define GEMM_STAGES 3
#define GEMM_SMEM_BYTES (GEMM_STAGES * STAGE_BYTES)

template <int ACT, int OUTMODE>
__device__ __forceinline__
void gemm_body(const __half* __restrict__ Ah, const __half* __restrict__ Wh,
               const float* __restrict__ bias,
               float* __restrict__ Cf, __half* __restrict__ Ch,
               int Nn, int K, int mBase, int nBase, char* dsm) {
    const uint32_t sb = s2u(dsm);

    const int tid  = threadIdx.x;
    const int wid  = tid >> 5;
    const int lane = tid & 31;
    const int wm   = wid & 1;        // 2 warps in m (64 rows each)
    const int wn   = wid >> 1;       // 4 warps in n (32 cols each)
    const int NC = K / 64;

    const int r0 = tid >> 3;
    const int c0 = tid & 7;

    const __half* pAh = Ah + (size_t)(mBase + r0) * K + c0 * 8;
    const __half* pWh = Wh + (size_t)(nBase + r0) * K + c0 * 8;

    auto load_stage = [&](int buf, int kcol) {
        const uint32_t stage = sb + buf * STAGE_BYTES;
#pragma unroll
        for (int j = 0; j < 4; j++) {
            const int r = r0 + 32 * j;
            const uint32_t off = SWZ((uint32_t)(r * 128 + c0 * 16));
            cp_async16(stage + off,         pAh + (size_t)(32 * j) * K + kcol);
            cp_async16(stage + 16384 + off, pWh + (size_t)(32 * j) * K + kcol);
        }
    };

    float acc[4][4][4];
#pragma unroll
    for (int i = 0; i < 4; i++)
#pragma unroll
        for (int j = 0; j < 4; j++)
#pragma unroll
            for (int t = 0; t < 4; t++) acc[i][j][t] = 0.f;

    const int aRow = wm * 64 + (lane & 15);
    const int aColSel = (lane >> 4) * 8;
    const int bRow = wn * 32 + ((lane >> 4) << 3) + (lane & 7);
    const int bColSel = ((lane >> 3) & 1) * 8;

    load_stage(0, 0);
    CP_COMMIT();
    load_stage(1, 64);
    CP_COMMIT();

    for (int c = 0; c < NC; c++) {
        if (c + 2 < NC) { CP_WAIT(1); }
        else            { CP_WAIT(0); }
        __syncthreads();

        const uint32_t stage = sb + (c % GEMM_STAGES) * STAGE_BYTES;
        const uint32_t sAh = stage, sWh = stage + 16384;

#pragma unroll
        for (int ks = 0; ks < 4; ks++) {
            const int kc = ks * 16;
            uint32_t ah[4][4];
#pragma unroll
            for (int fm = 0; fm < 4; fm++) {
                const uint32_t off = SWZ((uint32_t)((aRow + fm * 16) * 128 + (kc + aColSel) * 2));
                ldsm4(ah[fm], sAh + off);
            }
            uint32_t bh[4][2];
#pragma unroll
            for (int ng = 0; ng < 2; ng++) {
                const uint32_t off = SWZ((uint32_t)((bRow + ng * 16) * 128 + (kc + bColSel) * 2));
                uint32_t t[4];
                ldsm4(t, sWh + off);
                bh[ng*2][0] = t[0]; bh[ng*2][1] = t[1];
                bh[ng*2+1][0] = t[2]; bh[ng*2+1][1] = t[3];
            }
#pragma unroll
            for (int fm = 0; fm < 4; fm++)
#pragma unroll
                for (int fn = 0; fn < 4; fn++)
                    mma16816(acc[fm][fn], ah[fm], bh[fn]);
        }
        __syncthreads();

        if (c + 2 < NC) {
            load_stage((c + 2) % GEMM_STAGES, (c + 2) * 64);
            CP_COMMIT();
        }
    }

    // ---- epilogue ----
    const int erow = mBase + wm * 64 + (lane >> 2);
    const int ecol = nBase + wn * 32 + (lane & 3) * 2;
#pragma unroll
    for (int fm = 0; fm < 4; fm++) {
#pragma unroll
        for (int fn = 0; fn < 4; fn++) {
            const int col = ecol + fn * 8;
#pragma unroll
            for (int half = 0; half < 2; half++) {
                const int row = erow + fm * 16 + half * 8;
                float v0 = acc[fm][fn][half * 2 + 0];
                float v1 = acc[fm][fn][half * 2 + 1];
                if (bias) { v0 += bias[col]; v1 += bias[col + 1]; }
                if (ACT == 1) {
                    v0 = 0.5f * v0 * (1.f + erff(v0 * 0.70710678118654752f));
                    v1 = 0.5f * v1 * (1.f + erff(v1 * 0.70710678118654752f));
                }
                const size_t base = (size_t)row * Nn + col;
                if (OUTMODE == 1) {
                    *(uint32_t*)(Ch + base) = pack_h(v0, v1);
                } else {
                    *(float2*)(Cf + base) = make_float2(v0, v1);
                }
            }
        }
    }
}

template <int ACT, int OUTMODE>
__global__ __launch_bounds__(256, 2)
void mma_gemm(const __half* __restrict__ Ah, const __half* __restrict__ Wh,
              const float* __restrict__ bias,
              float* __restrict__ Cf, __half* __restrict__ Ch,
              int Nn, int K) {
    extern __shared__ char dsm[];
    gemm_body<ACT, OUTMODE>(Ah, Wh, bias, Cf, Ch,
                            Nn, K, blockIdx.y * 128, blockIdx.x * 128, dsm);
}

// fused QKV: gridDim.z selects which projection this CTA computes
__global__ __launch_bounds__(256, 2)
void qkv_gemm(const __half* __restrict__ Ah,
              const __half* __restrict__ Wq, const __half* __restrict__ Wk,
              const __half* __restrict__ Wv,
              __half* __restrict__ Cq, __half* __restrict__ Ck,
              __half* __restrict__ Cv) {
    extern __shared__ char dsm[];
    const int z = blockIdx.z;
    const __half* Wh = (z == 0) ? Wq : (z == 1) ? Wk : Wv;
    __half* Ch = (z == 0) ? Cq : (z == 1) ? Ck : Cv;
    gemm_body<0, 1>(Ah, Wh, nullptr, nullptr, Ch,
                    D_, D_, blockIdx.y * 128, blockIdx.x * 128, dsm);
}

// ---------------- flash attention, plain fp16: S=QK^T, O=PV -------------------------
// smem: Q[0,16K), stages at 16384 + s*16896: Kh +0, Vh +8192, coords +16384
#define ATT_STAGE 16896
#define ATT_SMEM  (16384 + 2 * ATT_STAGE)

__global__ __launch_bounds__(256, 2)
void attn_mma_kernel(const __half* __restrict__ qh,
                     const __half* __restrict__ kh,
                     const __half* __restrict__ vh,
                     const int* __restrict__ coords,
                     __half* __restrict__ aoh) {
    extern __shared__ char dsm[];
    const uint32_t sb = s2u(dsm);

    const int tid  = threadIdx.x;
    const int wid  = tid >> 5;
    const int lane = tid & 31;
    const int qt = blockIdx.x & 7;
    const int h  = (blockIdx.x >> 3) & 15;
    const int b  = blockIdx.x >> 7;
    const int qbase = qt * 128;

    const float slope = exp2f(-0.5f * (float)(h + 1));
    const float scale = 0.125f;

    const int r0 = wid * 16 + (lane >> 2);
    const int grow0 = b * N_ + qbase + r0;
    const float xi0 = (float)coords[grow0 * 2 + 0];
    const float yi0 = (float)coords[grow0 * 2 + 1];
    const float xi1 = (float)coords[(grow0 + 8) * 2 + 0];
    const float yi1 = (float)coords[(grow0 + 8) * 2 + 1];

    {   // Q (plain fp16, 16 KB)
        const int rr = tid >> 3, cc = tid & 7;
#pragma unroll
        for (int j = 0; j < 4; j++) {
            const int r = rr + 32 * j;
            const size_t go = (size_t)(b * N_ + qbase + r) * D_ + h * HD_ + cc * 8;
            cp_async16(sb + SWZ((uint32_t)(r * 128 + cc * 16)), qh + go);
        }
    }
    CP_COMMIT();

    auto load_kv = [&](int t, int buf) {
        const uint32_t st = sb + 16384 + buf * ATT_STAGE;
        const int kt = t * 64;
        const int rr = tid >> 2, cc = tid & 3;
        const size_t gbase = (size_t)(b * N_ + kt) * D_ + h * HD_;
#pragma unroll
        for (int j = 0; j < 2; j++) {
            const int ch = cc + 4 * j;
            const uint32_t off = SWZ((uint32_t)(rr * 128 + ch * 16));
            cp_async16(st + off,        kh + gbase + (size_t)rr * D_ + ch * 8);
            cp_async16(st + 8192 + off, vh + gbase + (size_t)rr * D_ + ch * 8);
        }
        if (tid < 32)
            cp_async16(st + 16384 + tid * 16,
                       (const char*)coords + (size_t)(b * N_ + kt) * 8 + tid * 16);
    };

    load_kv(0, 0);
    CP_COMMIT();

    float m0 = -1e30f, m1 = -1e30f, l0 = 0.f, l1 = 0.f;
    float acc_o[8][4];
#pragma unroll
    for (int f = 0; f < 8; f++)
#pragma unroll
        for (int t = 0; t < 4; t++) acc_o[f][t] = 0.f;

    const int aRow  = wid * 16 + (lane & 15);
    const int aCol  = (lane >> 4) * 8;
    const int bRowK = ((lane >> 4) << 3) + (lane & 7);
    const int bColK = ((lane >> 3) & 1) * 8;
    const int vRow  = ((lane >> 3) & 1) * 8 + (lane & 7);
    const int vCol  = (lane >> 4) * 8;

    for (int t = 0; t < 16; t++) {
        const int buf = t & 1;
        if (t + 1 < 16) { load_kv(t + 1, 1 - buf); CP_COMMIT(); CP_WAIT(1); }
        else            { CP_WAIT(0); }
        __syncthreads();

        const uint32_t st = sb + 16384 + buf * ATT_STAGE;
        const uint32_t sKh = st, sVh = st + 8192;
        const int2* kco = (const int2*)(dsm + 16384 + buf * ATT_STAGE + 16384);

        float accs[8][4];
#pragma unroll
        for (int f = 0; f < 8; f++)
#pragma unroll
            for (int u = 0; u < 4; u++) accs[f][u] = 0.f;

#pragma unroll
        for (int ks = 0; ks < 4; ks++) {
            const int kc = ks * 16;
            uint32_t ah[4];
            ldsm4(ah, sb + SWZ((uint32_t)(aRow * 128 + (kc + aCol) * 2)));
#pragma unroll
            for (int nh = 0; nh < 4; nh++) {
                const uint32_t boff = SWZ((uint32_t)((nh * 16 + bRowK) * 128 + (kc + bColK) * 2));
                uint32_t tb[4];
                ldsm4(tb, sKh + boff);
                uint32_t bh0[2] = { tb[0], tb[1] }, bh1[2] = { tb[2], tb[3] };
                mma16816(accs[nh*2],   ah, bh0);
                mma16816(accs[nh*2+1], ah, bh1);
            }
        }

#pragma unroll
        for (int f = 0; f < 8; f++) {
            const int c = f * 8 + (lane & 3) * 2;
            const int2 ca = kco[c], cb = kco[c + 1];
            const float xa = (float)ca.x, ya = (float)ca.y;
            const float xb = (float)cb.x, yb = (float)cb.y;
            accs[f][0] = fmaf(accs[f][0], scale, slope * (fabsf(xi0 - xa) + fabsf(yi0 - ya)));
            accs[f][1] = fmaf(accs[f][1], scale, slope * (fabsf(xi0 - xb) + fabsf(yi0 - yb)));
            accs[f][2] = fmaf(accs[f][2], scale, slope * (fabsf(xi1 - xa) + fabsf(yi1 - ya)));
            accs[f][3] = fmaf(accs[f][3], scale, slope * (fabsf(xi1 - xb) + fabsf(yi1 - yb)));
        }

        float mx0 = -1e30f, mx1 = -1e30f;
#pragma unroll
        for (int f = 0; f < 8; f++) {
            mx0 = fmaxf(mx0, fmaxf(accs[f][0], accs[f][1]));
            mx1 = fmaxf(mx1, fmaxf(accs[f][2], accs[f][3]));
        }
        mx0 = fmaxf(mx0, __shfl_xor_sync(0xffffffffu, mx0, 1));
        mx0 = fmaxf(mx0, __shfl_xor_sync(0xffffffffu, mx0, 2));
        mx1 = fmaxf(mx1, __shfl_xor_sync(0xffffffffu, mx1, 1));
        mx1 = fmaxf(mx1, __shfl_xor_sync(0xffffffffu, mx1, 2));
        const float nm0 = fmaxf(m0, mx0), nm1 = fmaxf(m1, mx1);
        const float cr0 = __expf(m0 - nm0), cr1 = __expf(m1 - nm1);
        m0 = nm0; m1 = nm1;
        l0 *= cr0; l1 *= cr1;
#pragma unroll
        for (int f = 0; f < 8; f++) {
            acc_o[f][0] *= cr0; acc_o[f][1] *= cr0;
            acc_o[f][2] *= cr1; acc_o[f][3] *= cr1;
        }
#pragma unroll
        for (int f = 0; f < 8; f++) {
            accs[f][0] = __expf(accs[f][0] - nm0);
            accs[f][1] = __expf(accs[f][1] - nm0);
            accs[f][2] = __expf(accs[f][2] - nm1);
            accs[f][3] = __expf(accs[f][3] - nm1);
            l0 += accs[f][0] + accs[f][1];
            l1 += accs[f][2] + accs[f][3];
        }

        // ---- O += P Vh (plain fp16 P) ----
#pragma unroll
        for (int kg = 0; kg < 4; kg++) {
            const float* s0 = accs[2 * kg];
            const float* s1 = accs[2 * kg + 1];
            uint32_t pa[4];
            pa[0] = pack_h(s0[0], s0[1]);
            pa[1] = pack_h(s0[2], s0[3]);
            pa[2] = pack_h(s1[0], s1[1]);
            pa[3] = pack_h(s1[2], s1[3]);
#pragma unroll
            for (int vi = 0; vi < 4; vi++) {
                const uint32_t voff =
                    SWZ((uint32_t)((kg * 16 + vRow) * 128 + (vi * 16 + vCol) * 2));
                uint32_t tv[4];
                ldsm4t(tv, sVh + voff);
                uint32_t bvh0[2] = { tv[0], tv[1] }, bvh1[2] = { tv[2], tv[3] };
                mma16816(acc_o[vi*2],   pa, bvh0);
                mma16816(acc_o[vi*2+1], pa, bvh1);
            }
        }
        __syncthreads();
    }

    l0 += __shfl_xor_sync(0xffffffffu, l0, 1);
    l0 += __shfl_xor_sync(0xffffffffu, l0, 2);
    l1 += __shfl_xor_sync(0xffffffffu, l1, 1);
    l1 += __shfl_xor_sync(0xffffffffu, l1, 2);
    const float inv0 = 1.f / l0, inv1 = 1.f / l1;
#pragma unroll
    for (int f = 0; f < 8; f++) {
        const int c = f * 8 + (lane & 3) * 2;
        const size_t base0 = (size_t)grow0 * D_ + h * HD_ + c;
        const size_t base1 = (size_t)(grow0 + 8) * D_ + h * HD_ + c;
        *(uint32_t*)(aoh + base0) = pack_h(acc_o[f][0] * inv0, acc_o[f][1] * inv0);
        *(uint32_t*)(aoh + base1) = pack_h(acc_o[f][2] * inv1, acc_o[f][3] * inv1);
    }
}

// ---------------- fused residual add + LayerNorm (+ optional plain fp16 emit) -------
__global__ __launch_bounds__(256)
void add_ln_kernel(const float* __restrict__ a, const float* __restrict__ bsum,
                   const float* __restrict__ g, const float* __restrict__ be,
                   float* __restrict__ out, __half* __restrict__ hi) {
    const int row = blockIdx.x;
    const int tid = threadIdx.x;
    const float* pa = a    + (size_t)row * D_;
    const float* pb = bsum + (size_t)row * D_;

    float v[4];
    float s = 0.f, ss = 0.f;
#pragma unroll
    for (int i = 0; i < 4; i++) {
        const int c = tid + 256 * i;
        const float t = pa[c] + pb[c];
        v[i] = t; s += t; ss = fmaf(t, t, ss);
    }
#pragma unroll
    for (int o = 16; o > 0; o >>= 1) {
        s  += __shfl_xor_sync(0xffffffffu, s,  o);
        ss += __shfl_xor_sync(0xffffffffu, ss, o);
    }
    __shared__ float rs[8], rss[8];
    __shared__ float smu, sinv;
    const int w = tid >> 5;
    if ((tid & 31) == 0) { rs[w] = s; rss[w] = ss; }
    __syncthreads();
    if (tid == 0) {
        float S = 0.f, SS = 0.f;
#pragma unroll
        for (int i = 0; i < 8; i++) { S += rs[i]; SS += rss[i]; }
        const float mu  = S * (1.f / 1024.f);
        const float var = SS * (1.f / 1024.f) - mu * mu;
        smu = mu; sinv = rsqrtf(var + 1e-5f);
    }
    __syncthreads();
    const float mu = smu, inv = sinv;
#pragma unroll
    for (int i = 0; i < 4; i++) {
        const int c = tid + 256 * i;
        const float o = (v[i] - mu) * inv * g[c] + be[c];
        out[(size_t)row * D_ + c] = o;
        if (hi) hi[(size_t)row * D_ + c] = __float2half_rn(o);
    }
}

// ---------------- launch ----------------
extern "C" void kernel_launch(void* const* d_in, const int* in_sizes, int n_in,
                              void* d_out, int out_size) {
    const float* src    = (const float*)d_in[0];
    const int*   coords = (const int*)  d_in[1];
    const float* Wq = (const float*)d_in[2];
    const float* Wk = (const float*)d_in[3];
    const float* Wv = (const float*)d_in[4];
    const float* Wo = (const float*)d_in[5];
    const float* W1 = (const float*)d_in[6];
    const float* b1 = (const float*)d_in[7];
    const float* W2 = (const float*)d_in[8];
    const float* b2 = (const float*)d_in[9];
    const float* g1 = (const float*)d_in[10];
    const float* be1= (const float*)d_in[11];
    const float* g2 = (const float*)d_in[12];
    const float* be2= (const float*)d_in[13];
    float* out = (float*)d_out;

    void *pt, *px;
    cudaGetSymbolAddress(&pt, g_t);
    cudaGetSymbolAddress(&px, g_x);

    void *srch,*wqh,*wkh,*wvh,*woh,*w1h,*w2h;
    void *xh,*aoh,*ffh,*qhh,*khh,*vhh;
    cudaGetSymbolAddress(&srch, s_src_h);
    cudaGetSymbolAddress(&wqh, s_wq_h);
    cudaGetSymbolAddress(&wkh, s_wk_h);
    cudaGetSymbolAddress(&wvh, s_wv_h);
    cudaGetSymbolAddress(&woh, s_wo_h);
    cudaGetSymbolAddress(&w1h, s_w1_h);
    cudaGetSymbolAddress(&w2h, s_w2_h);
    cudaGetSymbolAddress(&xh,  s_x_h);
    cudaGetSymbolAddress(&aoh, s_ao_h);
    cudaGetSymbolAddress(&ffh, s_ff_h);
    cudaGetSymbolAddress(&qhh, s_q_h);
    cudaGetSymbolAddress(&khh, s_k_h);
    cudaGetSymbolAddress(&vhh, s_v_h);

    cudaFuncSetAttribute((const void*)mma_gemm<0, 0>,
                         cudaFuncAttributeMaxDynamicSharedMemorySize, GEMM_SMEM_BYTES);
    cudaFuncSetAttribute((const void*)mma_gemm<0, 1>,
                         cudaFuncAttributeMaxDynamicSharedMemorySize, GEMM_SMEM_BYTES);
    cudaFuncSetAttribute((const void*)mma_gemm<1, 1>,
                         cudaFuncAttributeMaxDynamicSharedMemorySize, GEMM_SMEM_BYTES);
    cudaFuncSetAttribute((const void*)qkv_gemm,
                         cudaFuncAttributeMaxDynamicSharedMemorySize, GEMM_SMEM_BYTES);
    cudaFuncSetAttribute((const void*)attn_mma_kernel,
                         cudaFuncAttributeMaxDynamicSharedMemorySize, ATT_SMEM);

    const int nSrc4 = M_ * D_ / 4;     // 1,048,576 -> 4096 blocks
    const int nW4   = D_ * D_ / 4;     //   262,144 -> 1024 blocks
    const int nW14  = FF_ * D_ / 4;    // 1,048,576 -> 4096 blocks

    // batched convert: src, Wq, Wk, Wv, Wo, W1, W2 in ONE launch
    {
        CvtJobs jobs;
        const float4* srcs[CVT_JOBS] = {
            (const float4*)src, (const float4*)Wq, (const float4*)Wk,
            (const float4*)Wv, (const float4*)Wo, (const float4*)W1, (const float4*)W2 };
        uint2* dsts[CVT_JOBS] = {
            (uint2*)srch, (uint2*)wqh, (uint2*)wkh,
            (uint2*)wvh, (uint2*)woh, (uint2*)w1h, (uint2*)w2h };
        const int blks[CVT_JOBS] = {
            nSrc4 / 256, nW4 / 256, nW4 / 256, nW4 / 256,
            nW4 / 256, nW14 / 256, nW14 / 256 };
        int acc = 0;
        for (int j = 0; j < CVT_JOBS; j++) {
            jobs.src[j] = srcs[j];
            jobs.dst[j] = dsts[j];
            jobs.prefix[j] = acc;
            acc += blks[j];
        }
        jobs.prefix[CVT_JOBS] = acc;
        cvt_all_kernel<<<acc, 256>>>(jobs);
    }

    const dim3 blk(256);
    const dim3 gD(D_ / 128, M_ / 128);        // (8, 32)
    const dim3 gQKV(D_ / 128, M_ / 128, 3);   // (8, 32, 3)
    const dim3 gF(FF_ / 128, M_ / 128);       // (32, 32)

    // fused QKV projections
    qkv_gemm<<<gQKV, blk, GEMM_SMEM_BYTES>>>(
        (const __half*)srch,
        (const __half*)wqh, (const __half*)wkh, (const __half*)wvh,
        (__half*)qhh, (__half*)khh, (__half*)vhh);

    // flash attention
    attn_mma_kernel<<<512, 256, ATT_SMEM>>>(
        (const __half*)qhh, (const __half*)khh, (const __half*)vhh,
        coords, (__half*)aoh);

    // output projection -> fp32 t ; residual + LN1 -> x (fp32 + plain fp16)
    mma_gemm<0, 0><<<gD, blk, GEMM_SMEM_BYTES>>>(
        (const __half*)aoh, (const __half*)woh,
        nullptr, (float*)pt, nullptr, D_, D_);
    add_ln_kernel<<<M_, 256>>>(src, (const float*)pt, g1, be1, (float*)px, (__half*)xh);

    // FFN1 (bias + exact gelu; plain fp16 out)
    mma_gemm<1, 1><<<gF, blk, GEMM_SMEM_BYTES>>>(
        (const __half*)xh, (const __half*)w1h,
        b1, nullptr, (__half*)ffh, FF_, D_);

    // FFN2 (bias; fp32 out) ; residual + LN2 -> out
    mma_gemm<0, 0><<<gD, blk, GEMM_SMEM_BYTES>>>(
        (const __half*)ffh, (const __half*)w2h,
        b2, (float*)pt, nullptr, D_, FF_);
    add_ln_kernel<<<M_, 256>>>((const float*)px, (const float*)pt, g2, be2, out, nullptr);
}

// round 13
// speedup vs baseline: 2.5668x; 1.0199x over previous
#include <cuda_runtime.h>
#include <cuda_fp16.h>
#include <math.h>
#include <stdint.h>

#define B_   4
#define N_   1024
#define D_   1024
#define H_   16
#define HD_  64
#define FF_  4096
#define M_   (B_ * N_)   // 4096 rows

// ---------------- scratch (static device globals; no allocs allowed) ----------------
__device__ float g_t [M_ * D_];   // src2 / ffn2 output temp (fp32)
__device__ float g_x [M_ * D_];   // post-LN1 activations (fp32)

// plain fp16 buffers
__device__ __half s_src_h[M_ * D_];
__device__ __half s_wq_h [D_ * D_];
__device__ __half s_wk_h [D_ * D_];
__device__ __half s_wv_h [D_ * D_];
__device__ __half s_wo_h [D_ * D_];
__device__ __half s_w1_h [FF_ * D_];
__device__ __half s_w2_h [D_ * FF_];
__device__ __half s_x_h  [M_ * D_];
__device__ __half s_ao_h [M_ * D_];
__device__ __half s_ff_h [M_ * FF_];
__device__ __half s_q_h  [M_ * D_];
__device__ __half s_k_h  [M_ * D_];
__device__ __half s_v_h  [M_ * D_];

// ---------------- PTX helpers (Ampere-era only: valid at compute_103 base) ----------
__device__ __forceinline__ uint32_t s2u(const void* p) {
    uint32_t a;
    asm("{ .reg .u64 t; cvta.to.shared.u64 t, %1; cvt.u32.u64 %0, t; }" : "=r"(a) : "l"(p));
    return a;
}
__device__ __forceinline__ void cp_async16(uint32_t saddr, const void* g) {
    asm volatile("cp.async.cg.shared.global [%0], [%1], 16;" :: "r"(saddr), "l"(g) : "memory");
}
#define CP_COMMIT()  asm volatile("cp.async.commit_group;" ::: "memory")
#define CP_WAIT(n)   asm volatile("cp.async.wait_group %0;" :: "n"(n) : "memory")

__device__ __forceinline__ void ldsm4(uint32_t* r, uint32_t addr) {
    asm volatile("ldmatrix.sync.aligned.m8n8.x4.shared.b16 {%0,%1,%2,%3}, [%4];"
                 : "=r"(r[0]), "=r"(r[1]), "=r"(r[2]), "=r"(r[3]) : "r"(addr));
}
__device__ __forceinline__ void ldsm4t(uint32_t* r, uint32_t addr) {
    asm volatile("ldmatrix.sync.aligned.m8n8.x4.trans.shared.b16 {%0,%1,%2,%3}, [%4];"
                 : "=r"(r[0]), "=r"(r[1]), "=r"(r[2]), "=r"(r[3]) : "r"(addr));
}
__device__ __forceinline__ void mma16816(float* c, const uint32_t* a, const uint32_t* b) {
    asm volatile(
        "mma.sync.aligned.m16n8k16.row.col.f32.f16.f16.f32 "
        "{%0,%1,%2,%3}, {%4,%5,%6,%7}, {%8,%9}, {%0,%1,%2,%3};"
        : "+f"(c[0]), "+f"(c[1]), "+f"(c[2]), "+f"(c[3])
        : "r"(a[0]), "r"(a[1]), "r"(a[2]), "r"(a[3]), "r"(b[0]), "r"(b[1]));
}

#define SWZ(o) ((o) ^ (((o) >> 3) & 0x70))

__device__ __forceinline__ uint32_t pack_h(float a, float b) {
    __half2 hp = __halves2half2(__float2half_rn(a), __float2half_rn(b));
    return *(uint32_t*)&hp;
}

// ---------------- batched convert fp32 -> fp16 (all 7 tensors, one launch) ----------
#define CVT_JOBS 7
struct CvtJobs {
    const float4* src[CVT_JOBS];
    uint2*        dst[CVT_JOBS];
    int           prefix[CVT_JOBS + 1];  // block prefix sums
};

__global__ __launch_bounds__(256)
void cvt_all_kernel(CvtJobs jobs) {
    const int blk = blockIdx.x;
    int j = 0;
#pragma unroll
    for (int k = 1; k < CVT_JOBS; k++)
        if (blk >= jobs.prefix[k]) j = k;
    const int i = (blk - jobs.prefix[j]) * 256 + threadIdx.x;
    const int n4 = (jobs.prefix[j + 1] - jobs.prefix[j]) * 256;
    if (i >= n4) return;
    float4 v = jobs.src[j][i];
    jobs.dst[j][i] = make_uint2(pack_h(v.x, v.y), pack_h(v.z, v.w));
}

// ---------------- HMMA GEMM: C[M,Nn] = A[M,K] @ W[Nn,K]^T, plain fp16 ---------------
// 128x128 tile, 256 thr, warptile 64x32, BK=64, 3-stage cp.async, 2 CTAs/SM.
// Single barrier per chunk; next-stage loads issued BEFORE compute.
#define STAGE_BYTES 32768
#define GEMM_STAGES 3
#define GEMM_SMEM_BYTES (GEMM_STAGES * STAGE_BYTES)

template <int ACT, int OUTMODE>
__device__ __forceinline__
void gemm_body(const __half* __restrict__ Ah, const __half* __restrict__ Wh,
               const float* __restrict__ bias,
               float* __restrict__ Cf, __half* __restrict__ Ch,
               int Nn, int K, int mBase, int nBase, char* dsm) {
    const uint32_t sb = s2u(dsm);

    const int tid  = threadIdx.x;
    const int wid  = tid >> 5;
    const int lane = tid & 31;
    const int wm   = wid & 1;        // 2 warps in m (64 rows each)
    const int wn   = wid >> 1;       // 4 warps in n (32 cols each)
    const int NC = K / 64;

    const int r0 = tid >> 3;
    const int c0 = tid & 7;

    const __half* pAh = Ah + (size_t)(mBase + r0) * K + c0 * 8;
    const __half* pWh = Wh + (size_t)(nBase + r0) * K + c0 * 8;

    auto load_stage = [&](int buf, int kcol) {
        const uint32_t stage = sb + buf * STAGE_BYTES;
#pragma unroll
        for (int j = 0; j < 4; j++) {
            const int r = r0 + 32 * j;
            const uint32_t off = SWZ((uint32_t)(r * 128 + c0 * 16));
            cp_async16(stage + off,         pAh + (size_t)(32 * j) * K + kcol);
            cp_async16(stage + 16384 + off, pWh + (size_t)(32 * j) * K + kcol);
        }
    };

    float acc[4][4][4];
#pragma unroll
    for (int i = 0; i < 4; i++)
#pragma unroll
        for (int j = 0; j < 4; j++)
#pragma unroll
            for (int t = 0; t < 4; t++) acc[i][j][t] = 0.f;

    const int aRow = wm * 64 + (lane & 15);
    const int aColSel = (lane >> 4) * 8;
    const int bRow = wn * 32 + ((lane >> 4) << 3) + (lane & 7);
    const int bColSel = ((lane >> 3) & 1) * 8;

    load_stage(0, 0);
    CP_COMMIT();
    load_stage(1, 64);
    CP_COMMIT();

    for (int c = 0; c < NC; c++) {
        // wait until stage c is resident (leave the stage-(c+1) group in flight)
        if (c + 1 < NC) { CP_WAIT(1); }
        else            { CP_WAIT(0); }
        __syncthreads();   // also proves stage (c+2)%3 is no longer being read

        // issue next-stage loads BEFORE compute so they overlap the MMAs
        if (c + 2 < NC) {
            load_stage((c + 2) % GEMM_STAGES, (c + 2) * 64);
            CP_COMMIT();
        }

        const uint32_t stage = sb + (c % GEMM_STAGES) * STAGE_BYTES;
        const uint32_t sAh = stage, sWh = stage + 16384;

#pragma unroll
        for (int ks = 0; ks < 4; ks++) {
            const int kc = ks * 16;
            uint32_t ah[4][4];
#pragma unroll
            for (int fm = 0; fm < 4; fm++) {
                const uint32_t off = SWZ((uint32_t)((aRow + fm * 16) * 128 + (kc + aColSel) * 2));
                ldsm4(ah[fm], sAh + off);
            }
            uint32_t bh[4][2];
#pragma unroll
            for (int ng = 0; ng < 2; ng++) {
                const uint32_t off = SWZ((uint32_t)((bRow + ng * 16) * 128 + (kc + bColSel) * 2));
                uint32_t t[4];
                ldsm4(t, sWh + off);
                bh[ng*2][0] = t[0]; bh[ng*2][1] = t[1];
                bh[ng*2+1][0] = t[2]; bh[ng*2+1][1] = t[3];
            }
#pragma unroll
            for (int fm = 0; fm < 4; fm++)
#pragma unroll
                for (int fn = 0; fn < 4; fn++)
                    mma16816(acc[fm][fn], ah[fm], bh[fn]);
        }
        // no trailing barrier: top-of-next-chunk barrier provides the ordering
    }

    // ---- epilogue ----
    const int erow = mBase + wm * 64 + (lane >> 2);
    const int ecol = nBase + wn * 32 + (lane & 3) * 2;
#pragma unroll
    for (int fm = 0; fm < 4; fm++) {
#pragma unroll
        for (int fn = 0; fn < 4; fn++) {
            const int col = ecol + fn * 8;
#pragma unroll
            for (int half = 0; half < 2; half++) {
                const int row = erow + fm * 16 + half * 8;
                float v0 = acc[fm][fn][half * 2 + 0];
                float v1 = acc[fm][fn][half * 2 + 1];
                if (bias) { v0 += bias[col]; v1 += bias[col + 1]; }
                if (ACT == 1) {
                    v0 = 0.5f * v0 * (1.f + erff(v0 * 0.70710678118654752f));
                    v1 = 0.5f * v1 * (1.f + erff(v1 * 0.70710678118654752f));
                }
                const size_t base = (size_t)row * Nn + col;
                if (OUTMODE == 1) {
                    *(uint32_t*)(Ch + base) = pack_h(v0, v1);
                } else {
                    *(float2*)(Cf + base) = make_float2(v0, v1);
                }
            }
        }
    }
}

template <int ACT, int OUTMODE>
__global__ __launch_bounds__(256, 2)
void mma_gemm(const __half* __restrict__ Ah, const __half* __restrict__ Wh,
              const float* __restrict__ bias,
              float* __restrict__ Cf, __half* __restrict__ Ch,
              int Nn, int K) {
    extern __shared__ char dsm[];
    gemm_body<ACT, OUTMODE>(Ah, Wh, bias, Cf, Ch,
                            Nn, K, blockIdx.y * 128, blockIdx.x * 128, dsm);
}

// fused QKV: gridDim.z selects which projection this CTA computes
__global__ __launch_bounds__(256, 2)
void qkv_gemm(const __half* __restrict__ Ah,
              const __half* __restrict__ Wq, const __half* __restrict__ Wk,
              const __half* __restrict__ Wv,
              __half* __restrict__ Cq, __half* __restrict__ Ck,
              __half* __restrict__ Cv) {
    extern __shared__ char dsm[];
    const int z = blockIdx.z;
    const __half* Wh = (z == 0) ? Wq : (z == 1) ? Wk : Wv;
    __half* Ch = (z == 0) ? Cq : (z == 1) ? Ck : Cv;
    gemm_body<0, 1>(Ah, Wh, nullptr, nullptr, Ch,
                    D_, D_, blockIdx.y * 128, blockIdx.x * 128, dsm);
}

// ---------------- flash attention, plain fp16: S=QK^T, O=PV -------------------------
// smem: Q[0,16K), stages at 16384 + s*16896: Kh +0, Vh +8192, coords +16384
// Single barrier per KV tile; next-tile loads issued after the barrier.
#define ATT_STAGE 16896
#define ATT_SMEM  (16384 + 2 * ATT_STAGE)

__global__ __launch_bounds__(256, 2)
void attn_mma_kernel(const __half* __restrict__ qh,
                     const __half* __restrict__ kh,
                     const __half* __restrict__ vh,
                     const int* __restrict__ coords,
                     __half* __restrict__ aoh) {
    extern __shared__ char dsm[];
    const uint32_t sb = s2u(dsm);

    const int tid  = threadIdx.x;
    const int wid  = tid >> 5;
    const int lane = tid & 31;
    const int qt = blockIdx.x & 7;
    const int h  = (blockIdx.x >> 3) & 15;
    const int b  = blockIdx.x >> 7;
    const int qbase = qt * 128;

    const float slope = exp2f(-0.5f * (float)(h + 1));
    const float scale = 0.125f;

    const int r0 = wid * 16 + (lane >> 2);
    const int grow0 = b * N_ + qbase + r0;
    const float xi0 = (float)coords[grow0 * 2 + 0];
    const float yi0 = (float)coords[grow0 * 2 + 1];
    const float xi1 = (float)coords[(grow0 + 8) * 2 + 0];
    const float yi1 = (float)coords[(grow0 + 8) * 2 + 1];

    {   // Q (plain fp16, 16 KB)
        const int rr = tid >> 3, cc = tid & 7;
#pragma unroll
        for (int j = 0; j < 4; j++) {
            const int r = rr + 32 * j;
            const size_t go = (size_t)(b * N_ + qbase + r) * D_ + h * HD_ + cc * 8;
            cp_async16(sb + SWZ((uint32_t)(r * 128 + cc * 16)), qh + go);
        }
    }

    auto load_kv = [&](int t, int buf) {
        const uint32_t st = sb + 16384 + buf * ATT_STAGE;
        const int kt = t * 64;
        const int rr = tid >> 2, cc = tid & 3;
        const size_t gbase = (size_t)(b * N_ + kt) * D_ + h * HD_;
#pragma unroll
        for (int j = 0; j < 2; j++) {
            const int ch = cc + 4 * j;
            const uint32_t off = SWZ((uint32_t)(rr * 128 + ch * 16));
            cp_async16(st + off,        kh + gbase + (size_t)rr * D_ + ch * 8);
            cp_async16(st + 8192 + off, vh + gbase + (size_t)rr * D_ + ch * 8);
        }
        if (tid < 32)
            cp_async16(st + 16384 + tid * 16,
                       (const char*)coords + (size_t)(b * N_ + kt) * 8 + tid * 16);
    };

    load_kv(0, 0);   // Q + KV0 in one group
    CP_COMMIT();

    float m0 = -1e30f, m1 = -1e30f, l0 = 0.f, l1 = 0.f;
    float acc_o[8][4];
#pragma unroll
    for (int f = 0; f < 8; f++)
#pragma unroll
        for (int t = 0; t < 4; t++) acc_o[f][t] = 0.f;

    const int aRow  = wid * 16 + (lane & 15);
    const int aCol  = (lane >> 4) * 8;
    const int bRowK = ((lane >> 4) << 3) + (lane & 7);
    const int bColK = ((lane >> 3) & 1) * 8;
    const int vRow  = ((lane >> 3) & 1) * 8 + (lane & 7);
    const int vCol  = (lane >> 4) * 8;

    for (int t = 0; t < 16; t++) {
        const int buf = t & 1;
        CP_WAIT(0);        // tile t resident (issued during tile t-1)
        __syncthreads();   // also proves buffer 1-buf no longer being read

        if (t + 1 < 16) {  // overlap next-tile loads with this tile's compute
            load_kv(t + 1, 1 - buf);
            CP_COMMIT();
        }

        const uint32_t st = sb + 16384 + buf * ATT_STAGE;
        const uint32_t sKh = st, sVh = st + 8192;
        const int2* kco = (const int2*)(dsm + 16384 + buf * ATT_STAGE + 16384);

        float accs[8][4];
#pragma unroll
        for (int f = 0; f < 8; f++)
#pragma unroll
            for (int u = 0; u < 4; u++) accs[f][u] = 0.f;

#pragma unroll
        for (int ks = 0; ks < 4; ks++) {
            const int kc = ks * 16;
            uint32_t ah[4];
            ldsm4(ah, sb + SWZ((uint32_t)(aRow * 128 + (kc + aCol) * 2)));
#pragma unroll
            for (int nh = 0; nh < 4; nh++) {
                const uint32_t boff = SWZ((uint32_t)((nh * 16 + bRowK) * 128 + (kc + bColK) * 2));
                uint32_t tb[4];
                ldsm4(tb, sKh + boff);
                uint32_t bh0[2] = { tb[0], tb[1] }, bh1[2] = { tb[2], tb[3] };
                mma16816(accs[nh*2],   ah, bh0);
                mma16816(accs[nh*2+1], ah, bh1);
            }
        }

#pragma unroll
        for (int f = 0; f < 8; f++) {
            const int c = f * 8 + (lane & 3) * 2;
            const int2 ca = kco[c], cb = kco[c + 1];
            const float xa = (float)ca.x, ya = (float)ca.y;
            const float xb = (float)cb.x, yb = (float)cb.y;
            accs[f][0] = fmaf(accs[f][0], scale, slope * (fabsf(xi0 - xa) + fabsf(yi0 - ya)));
            accs[f][1] = fmaf(accs[f][1], scale, slope * (fabsf(xi0 - xb) + fabsf(yi0 - yb)));
            accs[f][2] = fmaf(accs[f][2], scale, slope * (fabsf(xi1 - xa) + fabsf(yi1 - ya)));
            accs[f][3] = fmaf(accs[f][3], scale, slope * (fabsf(xi1 - xb) + fabsf(yi1 - yb)));
        }

        float mx0 = -1e30f, mx1 = -1e30f;
#pragma unroll
        for (int f = 0; f < 8; f++) {
            mx0 = fmaxf(mx0, fmaxf(accs[f][0], accs[f][1]));
            mx1 = fmaxf(mx1, fmaxf(accs[f][2], accs[f][3]));
        }
        mx0 = fmaxf(mx0, __shfl_xor_sync(0xffffffffu, mx0, 1));
        mx0 = fmaxf(mx0, __shfl_xor_sync(0xffffffffu, mx0, 2));
        mx1 = fmaxf(mx1, __shfl_xor_sync(0xffffffffu, mx1, 1));
        mx1 = fmaxf(mx1, __shfl_xor_sync(0xffffffffu, mx1, 2));
        const float nm0 = fmaxf(m0, mx0), nm1 = fmaxf(m1, mx1);
        const float cr0 = __expf(m0 - nm0), cr1 = __expf(m1 - nm1);
        m0 = nm0; m1 = nm1;
        l0 *= cr0; l1 *= cr1;
#pragma unroll
        for (int f = 0; f < 8; f++) {
            acc_o[f][0] *= cr0; acc_o[f][1] *= cr0;
            acc_o[f][2] *= cr1; acc_o[f][3] *= cr1;
        }
#pragma unroll
        for (int f = 0; f < 8; f++) {
            accs[f][0] = __expf(accs[f][0] - nm0);
            accs[f][1] = __expf(accs[f][1] - nm0);
            accs[f][2] = __expf(accs[f][2] - nm1);
            accs[f][3] = __expf(accs[f][3] - nm1);
            l0 += accs[f][0] + accs[f][1];
            l1 += accs[f][2] + accs[f][3];
        }

        // ---- O += P Vh (plain fp16 P) ----
#pragma unroll
        for (int kg = 0; kg < 4; kg++) {
            const float* s0 = accs[2 * kg];
            const float* s1 = accs[2 * kg + 1];
            uint32_t pa[4];
            pa[0] = pack_h(s0[0], s0[1]);
            pa[1] = pack_h(s0[2], s0[3]);
            pa[2] = pack_h(s1[0], s1[1]);
            pa[3] = pack_h(s1[2], s1[3]);
#pragma unroll
            for (int vi = 0; vi < 4; vi++) {
                const uint32_t voff =
                    SWZ((uint32_t)((kg * 16 + vRow) * 128 + (vi * 16 + vCol) * 2));
                uint32_t tv[4];
                ldsm4t(tv, sVh + voff);
                uint32_t bvh0[2] = { tv[0], tv[1] }, bvh1[2] = { tv[2], tv[3] };
                mma16816(acc_o[vi*2],   pa, bvh0);
                mma16816(acc_o[vi*2+1], pa, bvh1);
            }
        }
        // no trailing barrier: next tile's top barrier provides ordering
    }

    l0 += __shfl_xor_sync(0xffffffffu, l0, 1);
    l0 += __shfl_xor_sync(0xffffffffu, l0, 2);
    l1 += __shfl_xor_sync(0xffffffffu, l1, 1);
    l1 += __shfl_xor_sync(0xffffffffu, l1, 2);
    const float inv0 = 1.f / l0, inv1 = 1.f / l1;
#pragma unroll
    for (int f = 0; f < 8; f++) {
        const int c = f * 8 + (lane & 3) * 2;
        const size_t base0 = (size_t)grow0 * D_ + h * HD_ + c;
        const size_t base1 = (size_t)(grow0 + 8) * D_ + h * HD_ + c;
        *(uint32_t*)(aoh + base0) = pack_h(acc_o[f][0] * inv0, acc_o[f][1] * inv0);
        *(uint32_t*)(aoh + base1) = pack_h(acc_o[f][2] * inv1, acc_o[f][3] * inv1);
    }
}

// ---------------- fused residual add + LayerNorm (+ optional plain fp16 emit) -------
__global__ __launch_bounds__(256)
void add_ln_kernel(const float* __restrict__ a, const float* __restrict__ bsum,
                   const float* __restrict__ g, const float* __restrict__ be,
                   float* __restrict__ out, __half* __restrict__ hi) {
    const int row = blockIdx.x;
    const int tid = threadIdx.x;
    const float* pa = a    + (size_t)row * D_;
    const float* pb = bsum + (size_t)row * D_;

    float v[4];
    float s = 0.f, ss = 0.f;
#pragma unroll
    for (int i = 0; i < 4; i++) {
        const int c = tid + 256 * i;
        const float t = pa[c] + pb[c];
        v[i] = t; s += t; ss = fmaf(t, t, ss);
    }
#pragma unroll
    for (int o = 16; o > 0; o >>= 1) {
        s  += __shfl_xor_sync(0xffffffffu, s,  o);
        ss += __shfl_xor_sync(0xffffffffu, ss, o);
    }
    __shared__ float rs[8], rss[8];
    __shared__ float smu, sinv;
    const int w = tid >> 5;
    if ((tid & 31) == 0) { rs[w] = s; rss[w] = ss; }
    __syncthreads();
    if (tid == 0) {
        float S = 0.f, SS = 0.f;
#pragma unroll
        for (int i = 0; i < 8; i++) { S += rs[i]; SS += rss[i]; }
        const float mu  = S * (1.f / 1024.f);
        const float var = SS * (1.f / 1024.f) - mu * mu;
        smu = mu; sinv = rsqrtf(var + 1e-5f);
    }
    __syncthreads();
    const float mu = smu, inv = sinv;
#pragma unroll
    for (int i = 0; i < 4; i++) {
        const int c = tid + 256 * i;
        const float o = (v[i] - mu) * inv * g[c] + be[c];
        out[(size_t)row * D_ + c] = o;
        if (hi) hi[(size_t)row * D_ + c] = __float2half_rn(o);
    }
}

// ---------------- launch ----------------
extern "C" void kernel_launch(void* const* d_in, const int* in_sizes, int n_in,
                              void* d_out, int out_size) {
    const float* src    = (const float*)d_in[0];
    const int*   coords = (const int*)  d_in[1];
    const float* Wq = (const float*)d_in[2];
    const float* Wk = (const float*)d_in[3];
    const float* Wv = (const float*)d_in[4];
    const float* Wo = (const float*)d_in[5];
    const float* W1 = (const float*)d_in[6];
    const float* b1 = (const float*)d_in[7];
    const float* W2 = (const float*)d_in[8];
    const float* b2 = (const float*)d_in[9];
    const float* g1 = (const float*)d_in[10];
    const float* be1= (const float*)d_in[11];
    const float* g2 = (const float*)d_in[12];
    const float* be2= (const float*)d_in[13];
    float* out = (float*)d_out;

    void *pt, *px;
    cudaGetSymbolAddress(&pt, g_t);
    cudaGetSymbolAddress(&px, g_x);

    void *srch,*wqh,*wkh,*wvh,*woh,*w1h,*w2h;
    void *xh,*aoh,*ffh,*qhh,*khh,*vhh;
    cudaGetSymbolAddress(&srch, s_src_h);
    cudaGetSymbolAddress(&wqh, s_wq_h);
    cudaGetSymbolAddress(&wkh, s_wk_h);
    cudaGetSymbolAddress(&wvh, s_wv_h);
    cudaGetSymbolAddress(&woh, s_wo_h);
    cudaGetSymbolAddress(&w1h, s_w1_h);
    cudaGetSymbolAddress(&w2h, s_w2_h);
    cudaGetSymbolAddress(&xh,  s_x_h);
    cudaGetSymbolAddress(&aoh, s_ao_h);
    cudaGetSymbolAddress(&ffh, s_ff_h);
    cudaGetSymbolAddress(&qhh, s_q_h);
    cudaGetSymbolAddress(&khh, s_k_h);
    cudaGetSymbolAddress(&vhh, s_v_h);

    cudaFuncSetAttribute((const void*)mma_gemm<0, 0>,
                         cudaFuncAttributeMaxDynamicSharedMemorySize, GEMM_SMEM_BYTES);
    cudaFuncSetAttribute((const void*)mma_gemm<0, 1>,
                         cudaFuncAttributeMaxDynamicSharedMemorySize, GEMM_SMEM_BYTES);
    cudaFuncSetAttribute((const void*)mma_gemm<1, 1>,
                         cudaFuncAttributeMaxDynamicSharedMemorySize, GEMM_SMEM_BYTES);
    cudaFuncSetAttribute((const void*)qkv_gemm,
                         cudaFuncAttributeMaxDynamicSharedMemorySize, GEMM_SMEM_BYTES);
    cudaFuncSetAttribute((const void*)attn_mma_kernel,
                         cudaFuncAttributeMaxDynamicSharedMemorySize, ATT_SMEM);

    const int nSrc4 = M_ * D_ / 4;     // 1,048,576 -> 4096 blocks
    const int nW4   = D_ * D_ / 4;     //   262,144 -> 1024 blocks
    const int nW14  = FF_ * D_ / 4;    // 1,048,576 -> 4096 blocks

    // batched convert: src, Wq, Wk, Wv, Wo, W1, W2 in ONE launch
    {
        CvtJobs jobs;
        const float4* srcs[CVT_JOBS] = {
            (const float4*)src, (const float4*)Wq, (const float4*)Wk,
            (const float4*)Wv, (const float4*)Wo, (const float4*)W1, (const float4*)W2 };
        uint2* dsts[CVT_JOBS] = {
            (uint2*)srch, (uint2*)wqh, (uint2*)wkh,
            (uint2*)wvh, (uint2*)woh, (uint2*)w1h, (uint2*)w2h };
        const int blks[CVT_JOBS] = {
            nSrc4 / 256, nW4 / 256, nW4 / 256, nW4 / 256,
            nW4 / 256, nW14 / 256, nW14 / 256 };
        int acc = 0;
        for (int j = 0; j < CVT_JOBS; j++) {
            jobs.src[j] = srcs[j];
            jobs.dst[j] = dsts[j];
            jobs.prefix[j] = acc;
            acc += blks[j];
        }
        jobs.prefix[CVT_JOBS] = acc;
        cvt_all_kernel<<<acc, 256>>>(jobs);
    }

    const dim3 blk(256);
    const dim3 gD(D_ / 128, M_ / 128);        // (8, 32)
    const dim3 gQKV(D_ / 128, M_ / 128, 3);   // (8, 32, 3)
    const dim3 gF(FF_ / 128, M_ / 128);       // (32, 32)

    // fused QKV projections
    qkv_gemm<<<gQKV, blk, GEMM_SMEM_BYTES>>>(
        (const __half*)srch,
        (const __half*)wqh, (const __half*)wkh, (const __half*)wvh,
        (__half*)qhh, (__half*)khh, (__half*)vhh);

    // flash attention
    attn_mma_kernel<<<512, 256, ATT_SMEM>>>(
        (const __half*)qhh, (const __half*)khh, (const __half*)vhh,
        coords, (__half*)aoh);

    // output projection -> fp32 t ; residual + LN1 -> x (fp32 + plain fp16)
    mma_gemm<0, 0><<<gD, blk, GEMM_SMEM_BYTES>>>(
        (const __half*)aoh, (const __half*)woh,
        nullptr, (float*)pt, nullptr, D_, D_);
    add_ln_kernel<<<M_, 256>>>(src, (const float*)pt, g1, be1, (float*)px, (__half*)xh);

    // FFN1 (bias + exact gelu; plain fp16 out)
    mma_gemm<1, 1><<<gF, blk, GEMM_SMEM_BYTES>>>(
        (const __half*)xh, (const __half*)w1h,
        b1, nullptr, (__half*)ffh, FF_, D_);

    // FFN2 (bias; fp32 out) ; residual + LN2 -> out
    mma_gemm<0, 0><<<gD, blk, GEMM_SMEM_BYTES>>>(
        (const __half*)ffh, (const __half*)w2h,
        b2, (float*)pt, nullptr, D_, FF_);
    add_ln_kernel<<<M_, 256>>>((const float*)px, (const float*)pt, g2, be2, out, nullptr);
}